// round 9
// baseline (speedup 1.0000x reference)
#include <cuda_runtime.h>
#include <cuda_bf16.h>
#include <math.h>
#include <stdint.h>

#define SS   2048
#define HIDD 2048
#define NH   16
#define HD   256
#define RR   64
#define NOPE 192
#define QLAT 1024
#define ORNK 512
#define NG   4
#define EPSV 1e-6f
#define SCL  0.0625f

typedef __nv_bfloat16 bf16;
typedef __nv_bfloat162 bf162;

// ---------------- scratch (static device globals; no allocations) ----------
__device__ float g_qa[SS * QLAT];
__device__ float g_q [SS * NH * HD];     // q up-proj; flash reads Q / writes O here
__device__ float g_kv[SS * HD];
__device__ float g_or[SS * NG * ORNK];
__device__ bf16 g_kvh[SS * HD], g_kvl[SS * HD];

__device__ __forceinline__ float rna_tf32(float x) {
    uint32_t r;
    asm("cvt.rna.tf32.f32 %0, %1;" : "=r"(r) : "f"(x));
    return __uint_as_float(r);
}
__device__ __forceinline__ uint32_t rna_u32(float x) {
    uint32_t r;
    asm("cvt.rna.tf32.f32 %0, %1;" : "=r"(r) : "f"(x));
    return r;
}
// split float pair into packed hi/lo bf16x2
__device__ __forceinline__ void split2(float x, float y, uint32_t& h, uint32_t& l) {
    bf162 hp, lp;
    hp.x = __float2bfloat16_rn(x);
    hp.y = __float2bfloat16_rn(y);
    lp.x = __float2bfloat16_rn(x - __bfloat162float(hp.x));
    lp.y = __float2bfloat16_rn(y - __bfloat162float(hp.y));
    h = *(uint32_t*)&hp;
    l = *(uint32_t*)&lp;
}
__device__ __forceinline__ uint32_t smem_u32(const void* p) {
    return (uint32_t)__cvta_generic_to_shared(p);
}
__device__ __forceinline__ void ldsm4(uint32_t addr, uint32_t* r) {
    asm volatile("ldmatrix.sync.aligned.m8n8.x4.shared.b16 {%0,%1,%2,%3}, [%4];"
                 : "=r"(r[0]), "=r"(r[1]), "=r"(r[2]), "=r"(r[3]) : "r"(addr));
}
__device__ __forceinline__ void ldsm4t(uint32_t addr, uint32_t* r) {
    asm volatile("ldmatrix.sync.aligned.m8n8.x4.trans.shared.b16 {%0,%1,%2,%3}, [%4];"
                 : "=r"(r[0]), "=r"(r[1]), "=r"(r[2]), "=r"(r[3]) : "r"(addr));
}
__device__ __forceinline__ void mma_bf16(float* d, const uint32_t* a, const uint32_t* b) {
    asm volatile(
        "mma.sync.aligned.m16n8k16.row.col.f32.bf16.bf16.f32 "
        "{%0,%1,%2,%3}, {%4,%5,%6,%7}, {%8,%9}, {%0,%1,%2,%3};"
        : "+f"(d[0]), "+f"(d[1]), "+f"(d[2]), "+f"(d[3])
        : "r"(a[0]), "r"(a[1]), "r"(a[2]), "r"(a[3]), "r"(b[0]), "r"(b[1]));
}

// ---------------- tf32 tensor-core NT GEMM (in-kernel RNA rounding) --------
#define TBM 128
#define TBN 128
#define TBK 32
#define ASTR 36
#define STG_F ((TBM + TBN) * ASTR)
#define NSTAGE 4
#define GEMM_SMEM (NSTAGE * STG_F * 4)

__global__ __launch_bounds__(256, 1) void gemm_tf32(
    const float* __restrict__ A, const float* __restrict__ B, float* __restrict__ C,
    int M, int N, int K, int lda, int ldb, int ldc,
    int group_n, int group_stride)
{
    extern __shared__ float sm[];
    const int bm0 = blockIdx.y * TBM;
    const int bn0 = blockIdx.x * TBN;
    const float* Ap = A + (group_n ? (bn0 / group_n) * (size_t)group_stride : 0);
    const int t = threadIdx.x;
    const int warp = t >> 5, lane = t & 31;
    const int wm = (warp >> 2) * 64, wn = (warp & 3) * 32;
    const int g = lane >> 2, tc = lane & 3;
    const int lrow = t >> 3, lc4 = (t & 7) * 4;

    float acc[4][4][4];
#pragma unroll
    for (int i = 0; i < 4; i++)
#pragma unroll
        for (int j = 0; j < 4; j++)
#pragma unroll
            for (int k = 0; k < 4; k++) acc[i][j][k] = 0.0f;

    const float* Agb = Ap + (size_t)(bm0 + lrow) * lda + lc4;
    const float* Bgb = B + (size_t)(bn0 + lrow) * ldb + lc4;

    auto issue = [&](int stage, int k0) {
        float* As = sm + stage * STG_F;
        float* Bs = As + TBM * ASTR;
        uint32_t sa = smem_u32(As + lrow * ASTR + lc4);
        uint32_t sb = smem_u32(Bs + lrow * ASTR + lc4);
        const float* ag = Agb + k0;
        const float* bg = Bgb + k0;
#pragma unroll
        for (int i = 0; i < 4; i++) {
            asm volatile("cp.async.cg.shared.global [%0], [%1], 16;"
                         :: "r"(sa + i * 32 * ASTR * 4), "l"(ag + (size_t)i * 32 * lda));
            asm volatile("cp.async.cg.shared.global [%0], [%1], 16;"
                         :: "r"(sb + i * 32 * ASTR * 4), "l"(bg + (size_t)i * 32 * ldb));
        }
        asm volatile("cp.async.commit_group;");
    };

    auto compute = [&](int stage) {
        const float* As = sm + stage * STG_F;
        const float* Bs = As + TBM * ASTR;
#pragma unroll
        for (int ks = 0; ks < 4; ks++) {
            uint32_t a[4][4], b[4][2];
#pragma unroll
            for (int am = 0; am < 4; am++) {
                const float* ap = As + (wm + am * 16 + g) * ASTR + ks * 8 + tc;
                a[am][0] = rna_u32(ap[0]);
                a[am][1] = rna_u32(ap[8 * ASTR]);
                a[am][2] = rna_u32(ap[4]);
                a[am][3] = rna_u32(ap[8 * ASTR + 4]);
            }
#pragma unroll
            for (int bn = 0; bn < 4; bn++) {
                const float* bp = Bs + (wn + bn * 8 + g) * ASTR + ks * 8 + tc;
                b[bn][0] = rna_u32(bp[0]);
                b[bn][1] = rna_u32(bp[4]);
            }
#pragma unroll
            for (int am = 0; am < 4; am++)
#pragma unroll
                for (int bn = 0; bn < 4; bn++)
                    asm volatile(
                        "mma.sync.aligned.m16n8k8.row.col.f32.tf32.tf32.f32 "
                        "{%0,%1,%2,%3}, {%4,%5,%6,%7}, {%8,%9}, {%0,%1,%2,%3};"
                        : "+f"(acc[am][bn][0]), "+f"(acc[am][bn][1]),
                          "+f"(acc[am][bn][2]), "+f"(acc[am][bn][3])
                        : "r"(a[am][0]), "r"(a[am][1]), "r"(a[am][2]), "r"(a[am][3]),
                          "r"(b[bn][0]), "r"(b[bn][1]));
        }
    };

    const int nk = K / TBK;
    issue(0, 0);
    issue(1, TBK);
    issue(2, 2 * TBK);

    for (int kt = 0; kt < nk; kt++) {
        asm volatile("cp.async.wait_group 2;");
        __syncthreads();
        compute(kt & 3);
        if (kt + 3 < nk) issue((kt + 3) & 3, (kt + 3) * TBK);
        else asm volatile("cp.async.commit_group;");
        __syncthreads();
    }

#pragma unroll
    for (int am = 0; am < 4; am++)
#pragma unroll
        for (int bn = 0; bn < 4; bn++) {
            int row0 = bm0 + wm + am * 16 + g;
            int col = bn0 + wn + bn * 8 + tc * 2;
            *(float2*)&C[(size_t)row0 * ldc + col] =
                make_float2(acc[am][bn][0], acc[am][bn][1]);
            *(float2*)&C[(size_t)(row0 + 8) * ldc + col] =
                make_float2(acc[am][bn][2], acc[am][bn][3]);
        }
}

// ---------------- rmsnorm over 1024 cols (in-place) ------------------------
__global__ void rmsnorm1024(float* __restrict__ x, const float* __restrict__ w)
{
    const int row = blockIdx.x;
    float* xr = x + row * QLAT;
    const int t = threadIdx.x; // 256
    float4 v = ((float4*)xr)[t];
    float ssq = v.x * v.x + v.y * v.y + v.z * v.z + v.w * v.w;
#pragma unroll
    for (int o = 16; o > 0; o >>= 1) ssq += __shfl_xor_sync(0xffffffffu, ssq, o);
    __shared__ float ws[8];
    if ((t & 31) == 0) ws[t >> 5] = ssq;
    __syncthreads();
    float tot = ws[0] + ws[1] + ws[2] + ws[3] + ws[4] + ws[5] + ws[6] + ws[7];
    float sc = rsqrtf(tot / (float)QLAT + EPSV);
    float4 wv = ((const float4*)w)[t];
    v.x *= sc * wv.x; v.y *= sc * wv.y; v.z *= sc * wv.z; v.w *= sc * wv.w;
    ((float4*)xr)[t] = v;
}

// ------- kv: rmsnorm(256) + rope on pe -> bf16 hi/lo -----------------------
__global__ void kv_norm_rope(const float* __restrict__ kv, const float* __restrict__ w,
                             const float* __restrict__ freqs,
                             bf16* __restrict__ kvh, bf16* __restrict__ kvl)
{
    const int s = blockIdx.x;
    const float* row = kv + s * HD;
    const int t = threadIdx.x; // 64
    float4 v = ((const float4*)row)[t];
    float ssq = v.x * v.x + v.y * v.y + v.z * v.z + v.w * v.w;
#pragma unroll
    for (int o = 16; o > 0; o >>= 1) ssq += __shfl_xor_sync(0xffffffffu, ssq, o);
    __shared__ float ws[2];
    if ((t & 31) == 0) ws[t >> 5] = ssq;
    __syncthreads();
    float sc = rsqrtf((ws[0] + ws[1]) / (float)HD + EPSV);
    float4 wv = ((const float4*)w)[t];
    v.x *= sc * wv.x; v.y *= sc * wv.y; v.z *= sc * wv.z; v.w *= sc * wv.w;
    const int c = t * 4;
    if (c >= NOPE) {
        int i0 = (c - NOPE) >> 1;
        float sn0, cs0, sn1, cs1;
        sincosf(freqs[s * (RR / 2) + i0], &sn0, &cs0);
        sincosf(freqs[s * (RR / 2) + i0 + 1], &sn1, &cs1);
        float x1 = v.x, x2 = v.y;
        v.x = x1 * cs0 - x2 * sn0; v.y = x1 * sn0 + x2 * cs0;
        x1 = v.z; x2 = v.w;
        v.z = x1 * cs1 - x2 * sn1; v.w = x1 * sn1 + x2 * cs1;
    }
    uint32_t h0, l0, h1, l1;
    split2(v.x, v.y, h0, l0);
    split2(v.z, v.w, h1, l1);
    *(uint2*)&kvh[s * HD + c] = make_uint2(h0, h1);
    *(uint2*)&kvl[s * HD + c] = make_uint2(l0, l1);
}

// ============ flash attention via bf16-split mma.sync (K == V) =============
// fused per-head q rmsnorm + rope + split in the CTA prologue.
#define QSTR 264
#define PSTR 72
#define QELE (64 * QSTR)
#define KOFF (2 * QELE)
#define KPAIR (2 * QELE)
#define POFF (KOFF + 2 * KPAIR)
#define PELE (64 * PSTR)
#define FL_SMEM ((POFF + 2 * PELE) * 2)

__global__ __launch_bounds__(256, 1) void flash_mma(
    float* __restrict__ qo,               // g_q: read Q, write O [s][h*256+d]
    const bf16* __restrict__ kvh, const bf16* __restrict__ kvl,
    const float* __restrict__ freqs,
    const float* __restrict__ sink)
{
    extern __shared__ __align__(16) bf16 smem[];
    __shared__ float red[2][2][64];

    const int qb = blockIdx.x;
    const int h  = blockIdx.y;
    const int t  = threadIdx.x;
    const int warp = t >> 5, lane = t & 31;
    const int wr = warp >> 1, wc = warp & 1;
    const int g = lane >> 2, tc = lane & 3;

    const uint32_t sb = smem_u32(smem);
    const int aRow = wr * 16 + (lane & 7) + ((lane >> 3) & 1) * 8;
    const int aCol8 = (lane >> 4) * 8;
    const int bRowQK = (lane & 7) + ((lane >> 4) & 1) * 8;
    const int bColQK8 = ((lane >> 3) & 1) * 8;
    const int bRowPV = (lane & 7) + ((lane >> 3) & 1) * 8;
    const int bColPV8 = ((lane >> 4) & 1) * 8;

    auto issue_kv = [&](int stage, int kb) {
        const size_t kbase = (size_t)(kb * 64) * HD;
        uint32_t koff = KOFF + stage * KPAIR;
        for (int i = t; i < 2048; i += 256) {
            int r = i >> 5, cb = i & 31;
            uint32_t dh = sb + (koff + r * QSTR + cb * 8) * 2;
            uint32_t dl = sb + (koff + QELE + r * QSTR + cb * 8) * 2;
            const bf16* srh = kvh + kbase + r * HD + cb * 8;
            const bf16* srl = kvl + kbase + r * HD + cb * 8;
            asm volatile("cp.async.cg.shared.global [%0], [%1], 16;" :: "r"(dh), "l"(srh));
            asm volatile("cp.async.cg.shared.global [%0], [%1], 16;" :: "r"(dl), "l"(srl));
        }
        asm volatile("cp.async.commit_group;");
    };
    issue_kv(0, 0);   // overlap KV stage 0 with Q prep

    // ---- fused Q prep: rms (no weight) + rope + hi/lo split -> smem ----
    {
        const int r = t >> 2, quad = t & 3;       // 4 threads per row
        const int srow = qb * 64 + r;
        const float* qrow = qo + (size_t)srow * (NH * HD) + h * HD + quad * 64;
        float ssq = 0.0f;
#pragma unroll
        for (int j = 0; j < 16; j++) {
            float4 v = ((const float4*)qrow)[j];
            ssq += v.x * v.x + v.y * v.y + v.z * v.z + v.w * v.w;
        }
        ssq += __shfl_xor_sync(0xffffffffu, ssq, 1);
        ssq += __shfl_xor_sync(0xffffffffu, ssq, 2);
        const float sc = rsqrtf(ssq / (float)HD + EPSV);
        const bool pe = (quad == 3);
#pragma unroll
        for (int j = 0; j < 16; j++) {
            float4 v = ((const float4*)qrow)[j];
            v.x *= sc; v.y *= sc; v.z *= sc; v.w *= sc;
            if (pe) {
                float sn, cs, x1, x2;
                sincosf(freqs[srow * (RR / 2) + 2 * j], &sn, &cs);
                x1 = v.x; x2 = v.y; v.x = x1 * cs - x2 * sn; v.y = x1 * sn + x2 * cs;
                sincosf(freqs[srow * (RR / 2) + 2 * j + 1], &sn, &cs);
                x1 = v.z; x2 = v.w; v.z = x1 * cs - x2 * sn; v.w = x1 * sn + x2 * cs;
            }
            uint32_t h0, l0, h1, l1;
            split2(v.x, v.y, h0, l0);
            split2(v.z, v.w, h1, l1);
            const int d = quad * 64 + j * 4;
            *(uint2*)(smem + r * QSTR + d) = make_uint2(h0, h1);
            *(uint2*)(smem + QELE + r * QSTR + d) = make_uint2(l0, l1);
        }
    }
    asm volatile("cp.async.wait_group 0;");
    __syncthreads();

    float Ot[16][4];
#pragma unroll
    for (int a = 0; a < 16; a++)
#pragma unroll
        for (int e = 0; e < 4; e++) Ot[a][e] = 0.0f;
    const float snk = sink[h];
    float m0 = snk, m1 = snk, l0 = 1.0f, l1 = 1.0f;

    const int grow0 = qb * 64 + wr * 16 + g;
    const int grow1 = grow0 + 8;
    const int lrow0 = wr * 16 + g;

    for (int kb = 0; kb <= qb; kb++) {
        const int cur = kb & 1;
        const uint32_t kh = KOFF + cur * KPAIR;
        const uint32_t kl = kh + QELE;

        float c[4][4];
#pragma unroll
        for (int a = 0; a < 4; a++)
#pragma unroll
            for (int e = 0; e < 4; e++) c[a][e] = 0.0f;

#pragma unroll 4
        for (int ks = 0; ks < 16; ks++) {
            const int k0 = ks * 16;
            uint32_t aH[4], aL[4];
            ldsm4(sb + (aRow * QSTR + k0 + aCol8) * 2, aH);
            ldsm4(sb + (QELE + aRow * QSTR + k0 + aCol8) * 2, aL);
#pragma unroll
            for (int pair = 0; pair < 2; pair++) {
                const int j0 = wc * 32 + pair * 16;
                uint32_t bH[4], bL[4];
                ldsm4(sb + (kh + (j0 + bRowQK) * QSTR + k0 + bColQK8) * 2, bH);
                ldsm4(sb + (kl + (j0 + bRowQK) * QSTR + k0 + bColQK8) * 2, bL);
#pragma unroll
                for (int s2 = 0; s2 < 2; s2++) {
                    float* cc = c[pair * 2 + s2];
                    mma_bf16(cc, aH, bH + s2 * 2);
                    mma_bf16(cc, aH, bL + s2 * 2);
                    mma_bf16(cc, aL, bH + s2 * 2);
                }
            }
        }

        if (kb < qb) issue_kv(cur ^ 1, kb + 1);
        else asm volatile("cp.async.commit_group;");

        const bool diag = (kb == qb);
#pragma unroll
        for (int a = 0; a < 4; a++) {
            int colb = kb * 64 + wc * 32 + a * 8 + 2 * tc;
            c[a][0] *= SCL; c[a][1] *= SCL; c[a][2] *= SCL; c[a][3] *= SCL;
            if (diag) {
                if (colb     > grow0) c[a][0] = -3.0e38f;
                if (colb + 1 > grow0) c[a][1] = -3.0e38f;
                if (colb     > grow1) c[a][2] = -3.0e38f;
                if (colb + 1 > grow1) c[a][3] = -3.0e38f;
            }
        }

        float tmax0 = -3.0e38f, tmax1 = -3.0e38f;
#pragma unroll
        for (int a = 0; a < 4; a++) {
            tmax0 = fmaxf(tmax0, fmaxf(c[a][0], c[a][1]));
            tmax1 = fmaxf(tmax1, fmaxf(c[a][2], c[a][3]));
        }
        tmax0 = fmaxf(tmax0, __shfl_xor_sync(0xffffffffu, tmax0, 1));
        tmax0 = fmaxf(tmax0, __shfl_xor_sync(0xffffffffu, tmax0, 2));
        tmax1 = fmaxf(tmax1, __shfl_xor_sync(0xffffffffu, tmax1, 1));
        tmax1 = fmaxf(tmax1, __shfl_xor_sync(0xffffffffu, tmax1, 2));
        if (tc == 0) {
            red[0][wc][lrow0] = tmax0;
            red[0][wc][lrow0 + 8] = tmax1;
        }
        __syncthreads();
        float mn0 = fmaxf(m0, fmaxf(red[0][0][lrow0], red[0][1][lrow0]));
        float mn1 = fmaxf(m1, fmaxf(red[0][0][lrow0 + 8], red[0][1][lrow0 + 8]));
        float alpha0 = __expf(m0 - mn0);
        float alpha1 = __expf(m1 - mn1);
#pragma unroll
        for (int a = 0; a < 16; a++) {
            Ot[a][0] *= alpha0; Ot[a][1] *= alpha0;
            Ot[a][2] *= alpha1; Ot[a][3] *= alpha1;
        }
        float tsum0 = 0.0f, tsum1 = 0.0f;
#pragma unroll
        for (int a = 0; a < 4; a++) {
            c[a][0] = __expf(c[a][0] - mn0);
            c[a][1] = __expf(c[a][1] - mn0);
            c[a][2] = __expf(c[a][2] - mn1);
            c[a][3] = __expf(c[a][3] - mn1);
            tsum0 += c[a][0] + c[a][1];
            tsum1 += c[a][2] + c[a][3];
        }
        tsum0 += __shfl_xor_sync(0xffffffffu, tsum0, 1);
        tsum0 += __shfl_xor_sync(0xffffffffu, tsum0, 2);
        tsum1 += __shfl_xor_sync(0xffffffffu, tsum1, 1);
        tsum1 += __shfl_xor_sync(0xffffffffu, tsum1, 2);
        if (tc == 0) {
            red[1][wc][lrow0] = tsum0;
            red[1][wc][lrow0 + 8] = tsum1;
        }
#pragma unroll
        for (int a = 0; a < 4; a++) {
            int cbase = wc * 32 + a * 8 + 2 * tc;
            uint32_t ph, pl;
            split2(c[a][0], c[a][1], ph, pl);
            *(uint32_t*)(smem + POFF + lrow0 * PSTR + cbase) = ph;
            *(uint32_t*)(smem + POFF + PELE + lrow0 * PSTR + cbase) = pl;
            split2(c[a][2], c[a][3], ph, pl);
            *(uint32_t*)(smem + POFF + (lrow0 + 8) * PSTR + cbase) = ph;
            *(uint32_t*)(smem + POFF + PELE + (lrow0 + 8) * PSTR + cbase) = pl;
        }
        __syncthreads();
        l0 = l0 * alpha0 + red[1][0][lrow0] + red[1][1][lrow0];
        l1 = l1 * alpha1 + red[1][0][lrow0 + 8] + red[1][1][lrow0 + 8];
        m0 = mn0; m1 = mn1;

#pragma unroll
        for (int ks = 0; ks < 4; ks++) {
            const int k0 = ks * 16;
            uint32_t pH[4], pL[4];
            ldsm4(sb + (POFF + aRow * PSTR + k0 + aCol8) * 2, pH);
            ldsm4(sb + (POFF + PELE + aRow * PSTR + k0 + aCol8) * 2, pL);
#pragma unroll
            for (int pair = 0; pair < 8; pair++) {
                const int n0 = wc * 128 + pair * 16;
                uint32_t vH[4], vL[4];
                ldsm4t(sb + (kh + (k0 + bRowPV) * QSTR + n0 + bColPV8) * 2, vH);
                ldsm4t(sb + (kl + (k0 + bRowPV) * QSTR + n0 + bColPV8) * 2, vL);
#pragma unroll
                for (int s2 = 0; s2 < 2; s2++) {
                    float* oo = Ot[pair * 2 + s2];
                    mma_bf16(oo, pH, vH + s2 * 2);
                    mma_bf16(oo, pH, vL + s2 * 2);
                    mma_bf16(oo, pL, vH + s2 * 2);
                }
            }
        }
        asm volatile("cp.async.wait_group 0;");
        __syncthreads();
    }

    const float inv0 = 1.0f / l0, inv1 = 1.0f / l1;
#pragma unroll
    for (int a = 0; a < 16; a++) {
        int col = h * HD + wc * 128 + a * 8 + 2 * tc;
        *(float2*)&qo[(size_t)grow0 * (NH * HD) + col] =
            make_float2(Ot[a][0] * inv0, Ot[a][1] * inv0);
        *(float2*)&qo[(size_t)grow1 * (NH * HD) + col] =
            make_float2(Ot[a][2] * inv1, Ot[a][3] * inv1);
    }
}

// ---------------- inverse rope on O pe part (in-place) ---------------------
__global__ void o_rope_inv(float* __restrict__ o, const float* __restrict__ freqs)
{
    const int s = blockIdx.x;
    const int t = threadIdx.x;       // 512
    const int h = t >> 5, i = t & 31;
    float sn, cs;
    sincosf(freqs[s * (RR / 2) + i], &sn, &cs);
    float* p = o + s * (NH * HD) + h * HD + NOPE + 2 * i;
    float x1 = p[0], x2 = p[1];
    p[0] = fmaf(x1, cs,  x2 * sn);
    p[1] = fmaf(x2, cs, -x1 * sn);
}

// ---------------- launch ---------------------------------------------------
extern "C" void kernel_launch(void* const* d_in, const int* in_sizes, int n_in,
                              void* d_out, int out_size)
{
    const float* x         = (const float*)d_in[0];
    const float* freqs     = (const float*)d_in[1];
    const float* wq_a      = (const float*)d_in[2];
    const float* q_norm_w  = (const float*)d_in[3];
    const float* wq_b      = (const float*)d_in[4];
    const float* wkv       = (const float*)d_in[5];
    const float* kv_norm_w = (const float*)d_in[6];
    const float* wo_a_w    = (const float*)d_in[7];
    const float* wo_b      = (const float*)d_in[8];
    const float* attn_sink = (const float*)d_in[9];
    float* out = (float*)d_out;

    float *qa, *q, *kv, *orr;
    bf16 *kvh, *kvl;
    cudaGetSymbolAddress((void**)&qa,  g_qa);
    cudaGetSymbolAddress((void**)&q,   g_q);
    cudaGetSymbolAddress((void**)&kv,  g_kv);
    cudaGetSymbolAddress((void**)&orr, g_or);
    cudaGetSymbolAddress((void**)&kvh, g_kvh);
    cudaGetSymbolAddress((void**)&kvl, g_kvl);

    cudaFuncSetAttribute(gemm_tf32, cudaFuncAttributeMaxDynamicSharedMemorySize, GEMM_SMEM);
    cudaFuncSetAttribute(flash_mma, cudaFuncAttributeMaxDynamicSharedMemorySize, FL_SMEM);

    // q_a = x @ wq_a^T   [2048,1024]
    gemm_tf32<<<dim3(QLAT / TBN, SS / TBM), 256, GEMM_SMEM>>>(       // 0
        x, wq_a, qa, SS, QLAT, HIDD, HIDD, HIDD, QLAT, 0, 0);
    rmsnorm1024<<<SS, 256>>>(qa, q_norm_w);                          // 1
    // q = rms(q_a) @ wq_b^T   [2048,4096]
    gemm_tf32<<<dim3((NH * HD) / TBN, SS / TBM), 256, GEMM_SMEM>>>(  // 2
        qa, wq_b, q, SS, NH * HD, QLAT, QLAT, QLAT, NH * HD, 0, 0);
    // kv = x @ wkv^T     [2048,256]
    gemm_tf32<<<dim3(HD / TBN, SS / TBM), 256, GEMM_SMEM>>>(         // 3
        x, wkv, kv, SS, HD, HIDD, HIDD, HIDD, HD, 0, 0);
    kv_norm_rope<<<SS, 64>>>(kv, kv_norm_w, freqs, kvh, kvl);        // 4
    // flash attention (fused q-prep) over g_q in-place                 5 <- profiled
    flash_mma<<<dim3(SS / 64, NH), 256, FL_SMEM>>>(q, kvh, kvl, freqs, attn_sink);
    o_rope_inv<<<SS, 512>>>(q, freqs);                               // 6
    // o_r = blockdiag(o @ wo_a^T)  [2048,2048]
    gemm_tf32<<<dim3((NG * ORNK) / TBN, SS / TBM), 256, GEMM_SMEM>>>( // 7
        q, wo_a_w, orr, SS, NG * ORNK, NG * HD, NH * HD, NG * HD, NG * ORNK, ORNK, NG * HD);
    // out = o_r @ wo_b^T [2048,2048]
    gemm_tf32<<<dim3(HIDD / TBN, SS / TBM), 256, GEMM_SMEM>>>(       // 8
        orr, wo_b, out, SS, HIDD, NG * ORNK, NG * ORNK, NG * ORNK, HIDD, 0, 0);
}

// round 10
// speedup vs baseline: 1.0797x; 1.0797x over previous
#include <cuda_runtime.h>
#include <cuda_bf16.h>
#include <math.h>
#include <stdint.h>

#define SS   2048
#define HIDD 2048
#define NH   16
#define HD   256
#define RR   64
#define NOPE 192
#define QLAT 1024
#define ORNK 512
#define NG   4
#define EPSV 1e-6f
#define SCL  0.0625f
#define KVSPLIT 4

typedef __nv_bfloat16 bf16;
typedef __nv_bfloat162 bf162;

// ---------------- scratch (static device globals; no allocations) ----------
__device__ float g_qa[SS * QLAT];
__device__ float g_q [SS * NH * HD];       // q up-proj; flash reads Q / writes O here
__device__ float g_kvp[KVSPLIT * SS * HD]; // kv split-K partials
__device__ float g_or[SS * NG * ORNK];
__device__ bf16 g_kvh[SS * HD], g_kvl[SS * HD];
// tf32-rounded operand copies
__device__ float g_xr [SS * HIDD];
__device__ float g_wqa[QLAT * HIDD];
__device__ float g_wqb[NH * HD * QLAT];
__device__ float g_wkv[HD * HIDD];
__device__ float g_woa[NG * ORNK * NG * HD];
__device__ float g_wob[HIDD * NG * ORNK];

__device__ __forceinline__ float rna_tf32(float x) {
    uint32_t r;
    asm("cvt.rna.tf32.f32 %0, %1;" : "=r"(r) : "f"(x));
    return __uint_as_float(r);
}
__device__ __forceinline__ void split2(float x, float y, uint32_t& h, uint32_t& l) {
    bf162 hp, lp;
    hp.x = __float2bfloat16_rn(x);
    hp.y = __float2bfloat16_rn(y);
    lp.x = __float2bfloat16_rn(x - __bfloat162float(hp.x));
    lp.y = __float2bfloat16_rn(y - __bfloat162float(hp.y));
    h = *(uint32_t*)&hp;
    l = *(uint32_t*)&lp;
}
__device__ __forceinline__ uint32_t smem_u32(const void* p) {
    return (uint32_t)__cvta_generic_to_shared(p);
}
__device__ __forceinline__ void ldsm4(uint32_t addr, uint32_t* r) {
    asm volatile("ldmatrix.sync.aligned.m8n8.x4.shared.b16 {%0,%1,%2,%3}, [%4];"
                 : "=r"(r[0]), "=r"(r[1]), "=r"(r[2]), "=r"(r[3]) : "r"(addr));
}
__device__ __forceinline__ void ldsm4t(uint32_t addr, uint32_t* r) {
    asm volatile("ldmatrix.sync.aligned.m8n8.x4.trans.shared.b16 {%0,%1,%2,%3}, [%4];"
                 : "=r"(r[0]), "=r"(r[1]), "=r"(r[2]), "=r"(r[3]) : "r"(addr));
}
__device__ __forceinline__ void mma_bf16(float* d, const uint32_t* a, const uint32_t* b) {
    asm volatile(
        "mma.sync.aligned.m16n8k16.row.col.f32.bf16.bf16.f32 "
        "{%0,%1,%2,%3}, {%4,%5,%6,%7}, {%8,%9}, {%0,%1,%2,%3};"
        : "+f"(d[0]), "+f"(d[1]), "+f"(d[2]), "+f"(d[3])
        : "r"(a[0]), "r"(a[1]), "r"(a[2]), "r"(a[3]), "r"(b[0]), "r"(b[1]));
}

// ---------------- elementwise tf32 rounding (float4) -----------------------
__global__ void round_tf32_vec(const float* __restrict__ in, float* __restrict__ out, int n4)
{
    int i = blockIdx.x * blockDim.x + threadIdx.x;
    if (i < n4) {
        float4 v = ((const float4*)in)[i];
        v.x = rna_tf32(v.x); v.y = rna_tf32(v.y);
        v.z = rna_tf32(v.z); v.w = rna_tf32(v.w);
        ((float4*)out)[i] = v;
    }
}

// ---------------- tf32 tensor-core NT GEMM: C = A[M,K] * B[N,K]^T ----------
// 4-stage cp.async pipeline, single barrier per iteration, optional split-K
// via blockIdx.z (partial planes of M*ldc each).
#define TBM 128
#define TBN 128
#define TBK 32
#define ASTR 36
#define STG_F ((TBM + TBN) * ASTR)
#define NSTAGE 4
#define GEMM_SMEM (NSTAGE * STG_F * 4)

__global__ __launch_bounds__(256, 1) void gemm_tf32(
    const float* __restrict__ A, const float* __restrict__ B, float* __restrict__ C,
    int M, int N, int K, int lda, int ldb, int ldc,
    int group_n, int group_stride, int round_out)
{
    extern __shared__ float sm[];
    const int bm0 = blockIdx.y * TBM;
    const int bn0 = blockIdx.x * TBN;
    const int Ksub = K / gridDim.z;
    const int kbase = blockIdx.z * Ksub;
    C += (size_t)blockIdx.z * M * ldc;
    const float* Ap = A + (group_n ? (bn0 / group_n) * (size_t)group_stride : 0);
    const int t = threadIdx.x;
    const int warp = t >> 5, lane = t & 31;
    const int wm = (warp >> 2) * 64, wn = (warp & 3) * 32;
    const int g = lane >> 2, tc = lane & 3;
    const int lrow = t >> 3, lc4 = (t & 7) * 4;

    float acc[4][4][4];
#pragma unroll
    for (int i = 0; i < 4; i++)
#pragma unroll
        for (int j = 0; j < 4; j++)
#pragma unroll
            for (int k = 0; k < 4; k++) acc[i][j][k] = 0.0f;

    const float* Agb = Ap + (size_t)(bm0 + lrow) * lda + kbase + lc4;
    const float* Bgb = B + (size_t)(bn0 + lrow) * ldb + kbase + lc4;

    auto issue = [&](int stage, int k0) {
        float* As = sm + stage * STG_F;
        float* Bs = As + TBM * ASTR;
        uint32_t sa = smem_u32(As + lrow * ASTR + lc4);
        uint32_t sb = smem_u32(Bs + lrow * ASTR + lc4);
        const float* ag = Agb + k0;
        const float* bg = Bgb + k0;
#pragma unroll
        for (int i = 0; i < 4; i++) {
            asm volatile("cp.async.cg.shared.global [%0], [%1], 16;"
                         :: "r"(sa + i * 32 * ASTR * 4), "l"(ag + (size_t)i * 32 * lda));
            asm volatile("cp.async.cg.shared.global [%0], [%1], 16;"
                         :: "r"(sb + i * 32 * ASTR * 4), "l"(bg + (size_t)i * 32 * ldb));
        }
        asm volatile("cp.async.commit_group;");
    };

    auto compute = [&](int stage) {
        const float* As = sm + stage * STG_F;
        const float* Bs = As + TBM * ASTR;
#pragma unroll
        for (int ks = 0; ks < 4; ks++) {
            uint32_t a[4][4], b[4][2];
#pragma unroll
            for (int am = 0; am < 4; am++) {
                const float* ap = As + (wm + am * 16 + g) * ASTR + ks * 8 + tc;
                a[am][0] = __float_as_uint(ap[0]);
                a[am][1] = __float_as_uint(ap[8 * ASTR]);
                a[am][2] = __float_as_uint(ap[4]);
                a[am][3] = __float_as_uint(ap[8 * ASTR + 4]);
            }
#pragma unroll
            for (int bn = 0; bn < 4; bn++) {
                const float* bp = Bs + (wn + bn * 8 + g) * ASTR + ks * 8 + tc;
                b[bn][0] = __float_as_uint(bp[0]);
                b[bn][1] = __float_as_uint(bp[4]);
            }
#pragma unroll
            for (int am = 0; am < 4; am++)
#pragma unroll
                for (int bn = 0; bn < 4; bn++)
                    asm volatile(
                        "mma.sync.aligned.m16n8k8.row.col.f32.tf32.tf32.f32 "
                        "{%0,%1,%2,%3}, {%4,%5,%6,%7}, {%8,%9}, {%0,%1,%2,%3};"
                        : "+f"(acc[am][bn][0]), "+f"(acc[am][bn][1]),
                          "+f"(acc[am][bn][2]), "+f"(acc[am][bn][3])
                        : "r"(a[am][0]), "r"(a[am][1]), "r"(a[am][2]), "r"(a[am][3]),
                          "r"(b[bn][0]), "r"(b[bn][1]));
        }
    };

    const int nk = Ksub / TBK;
    issue(0, 0);
    issue(1, TBK);
    issue(2, 2 * TBK);

    for (int kt = 0; kt < nk; kt++) {
        asm volatile("cp.async.wait_group 2;");
        __syncthreads();
        compute(kt & 3);
        if (kt + 3 < nk) issue((kt + 3) & 3, (kt + 3) * TBK);
        else asm volatile("cp.async.commit_group;");
    }

#pragma unroll
    for (int am = 0; am < 4; am++)
#pragma unroll
        for (int bn = 0; bn < 4; bn++) {
            int row0 = bm0 + wm + am * 16 + g;
            int col = bn0 + wn + bn * 8 + tc * 2;
            float2 v0 = make_float2(acc[am][bn][0], acc[am][bn][1]);
            float2 v1 = make_float2(acc[am][bn][2], acc[am][bn][3]);
            if (round_out) {
                v0.x = rna_tf32(v0.x); v0.y = rna_tf32(v0.y);
                v1.x = rna_tf32(v1.x); v1.y = rna_tf32(v1.y);
            }
            *(float2*)&C[(size_t)row0 * ldc + col] = v0;
            *(float2*)&C[(size_t)(row0 + 8) * ldc + col] = v1;
        }
}

// ---------------- rmsnorm over 1024 cols (in-place, tf32-round) ------------
__global__ void rmsnorm1024(float* __restrict__ x, const float* __restrict__ w)
{
    const int row = blockIdx.x;
    float* xr = x + row * QLAT;
    const int t = threadIdx.x; // 256
    float4 v = ((float4*)xr)[t];
    float ssq = v.x * v.x + v.y * v.y + v.z * v.z + v.w * v.w;
#pragma unroll
    for (int o = 16; o > 0; o >>= 1) ssq += __shfl_xor_sync(0xffffffffu, ssq, o);
    __shared__ float ws[8];
    if ((t & 31) == 0) ws[t >> 5] = ssq;
    __syncthreads();
    float tot = ws[0] + ws[1] + ws[2] + ws[3] + ws[4] + ws[5] + ws[6] + ws[7];
    float sc = rsqrtf(tot / (float)QLAT + EPSV);
    float4 wv = ((const float4*)w)[t];
    v.x = rna_tf32(v.x * sc * wv.x); v.y = rna_tf32(v.y * sc * wv.y);
    v.z = rna_tf32(v.z * sc * wv.z); v.w = rna_tf32(v.w * sc * wv.w);
    ((float4*)xr)[t] = v;
}

// --- kv: sum split-K partials + rmsnorm(256) + rope -> bf16 hi/lo ----------
__global__ void kv_norm_rope(const float* __restrict__ kvp, const float* __restrict__ w,
                             const float* __restrict__ freqs,
                             bf16* __restrict__ kvh, bf16* __restrict__ kvl)
{
    const int s = blockIdx.x;
    const int t = threadIdx.x; // 64
    float4 v = ((const float4*)(kvp + (size_t)s * HD))[t];
#pragma unroll
    for (int z = 1; z < KVSPLIT; z++) {
        float4 p = ((const float4*)(kvp + (size_t)z * SS * HD + (size_t)s * HD))[t];
        v.x += p.x; v.y += p.y; v.z += p.z; v.w += p.w;
    }
    float ssq = v.x * v.x + v.y * v.y + v.z * v.z + v.w * v.w;
#pragma unroll
    for (int o = 16; o > 0; o >>= 1) ssq += __shfl_xor_sync(0xffffffffu, ssq, o);
    __shared__ float ws[2];
    if ((t & 31) == 0) ws[t >> 5] = ssq;
    __syncthreads();
    float sc = rsqrtf((ws[0] + ws[1]) / (float)HD + EPSV);
    float4 wv = ((const float4*)w)[t];
    v.x *= sc * wv.x; v.y *= sc * wv.y; v.z *= sc * wv.z; v.w *= sc * wv.w;
    const int c = t * 4;
    if (c >= NOPE) {
        int i0 = (c - NOPE) >> 1;
        float sn0, cs0, sn1, cs1;
        sincosf(freqs[s * (RR / 2) + i0], &sn0, &cs0);
        sincosf(freqs[s * (RR / 2) + i0 + 1], &sn1, &cs1);
        float x1 = v.x, x2 = v.y;
        v.x = x1 * cs0 - x2 * sn0; v.y = x1 * sn0 + x2 * cs0;
        x1 = v.z; x2 = v.w;
        v.z = x1 * cs1 - x2 * sn1; v.w = x1 * sn1 + x2 * cs1;
    }
    uint32_t h0, l0, h1, l1;
    split2(v.x, v.y, h0, l0);
    split2(v.z, v.w, h1, l1);
    *(uint2*)&kvh[s * HD + c] = make_uint2(h0, h1);
    *(uint2*)&kvl[s * HD + c] = make_uint2(l0, l1);
}

// ============ flash attention via bf16-split mma.sync (K == V) =============
#define QSTR 264
#define PSTR 72
#define QELE (64 * QSTR)
#define KOFF (2 * QELE)
#define KPAIR (2 * QELE)
#define POFF (KOFF + 2 * KPAIR)
#define PELE (64 * PSTR)
#define FL_SMEM ((POFF + 2 * PELE) * 2)

__global__ __launch_bounds__(256, 1) void flash_mma(
    float* __restrict__ qo,
    const bf16* __restrict__ kvh, const bf16* __restrict__ kvl,
    const float* __restrict__ freqs,
    const float* __restrict__ sink)
{
    extern __shared__ __align__(16) bf16 smem[];
    __shared__ float red[2][2][64];

    const int qb = blockIdx.x;
    const int h  = blockIdx.y;
    const int t  = threadIdx.x;
    const int warp = t >> 5, lane = t & 31;
    const int wr = warp >> 1, wc = warp & 1;
    const int g = lane >> 2, tc = lane & 3;

    const uint32_t sb = smem_u32(smem);
    const int aRow = wr * 16 + (lane & 7) + ((lane >> 3) & 1) * 8;
    const int aCol8 = (lane >> 4) * 8;
    const int bRowQK = (lane & 7) + ((lane >> 4) & 1) * 8;
    const int bColQK8 = ((lane >> 3) & 1) * 8;
    const int bRowPV = (lane & 7) + ((lane >> 3) & 1) * 8;
    const int bColPV8 = ((lane >> 4) & 1) * 8;

    auto issue_kv = [&](int stage, int kb) {
        const size_t kbase = (size_t)(kb * 64) * HD;
        uint32_t koff = KOFF + stage * KPAIR;
        for (int i = t; i < 2048; i += 256) {
            int r = i >> 5, cb = i & 31;
            uint32_t dh = sb + (koff + r * QSTR + cb * 8) * 2;
            uint32_t dl = sb + (koff + QELE + r * QSTR + cb * 8) * 2;
            const bf16* srh = kvh + kbase + r * HD + cb * 8;
            const bf16* srl = kvl + kbase + r * HD + cb * 8;
            asm volatile("cp.async.cg.shared.global [%0], [%1], 16;" :: "r"(dh), "l"(srh));
            asm volatile("cp.async.cg.shared.global [%0], [%1], 16;" :: "r"(dl), "l"(srl));
        }
        asm volatile("cp.async.commit_group;");
    };
    issue_kv(0, 0);

    // fused Q prep: per-head rms + rope + hi/lo split -> smem
    {
        const int r = t >> 2, quad = t & 3;
        const int srow = qb * 64 + r;
        const float* qrow = qo + (size_t)srow * (NH * HD) + h * HD + quad * 64;
        float ssq = 0.0f;
#pragma unroll
        for (int j = 0; j < 16; j++) {
            float4 v = ((const float4*)qrow)[j];
            ssq += v.x * v.x + v.y * v.y + v.z * v.z + v.w * v.w;
        }
        ssq += __shfl_xor_sync(0xffffffffu, ssq, 1);
        ssq += __shfl_xor_sync(0xffffffffu, ssq, 2);
        const float sc = rsqrtf(ssq / (float)HD + EPSV);
        const bool pe = (quad == 3);
#pragma unroll
        for (int j = 0; j < 16; j++) {
            float4 v = ((const float4*)qrow)[j];
            v.x *= sc; v.y *= sc; v.z *= sc; v.w *= sc;
            if (pe) {
                float sn, cs, x1, x2;
                sincosf(freqs[srow * (RR / 2) + 2 * j], &sn, &cs);
                x1 = v.x; x2 = v.y; v.x = x1 * cs - x2 * sn; v.y = x1 * sn + x2 * cs;
                sincosf(freqs[srow * (RR / 2) + 2 * j + 1], &sn, &cs);
                x1 = v.z; x2 = v.w; v.z = x1 * cs - x2 * sn; v.w = x1 * sn + x2 * cs;
            }
            uint32_t h0, l0, h1, l1;
            split2(v.x, v.y, h0, l0);
            split2(v.z, v.w, h1, l1);
            const int d = quad * 64 + j * 4;
            *(uint2*)(smem + r * QSTR + d) = make_uint2(h0, h1);
            *(uint2*)(smem + QELE + r * QSTR + d) = make_uint2(l0, l1);
        }
    }
    asm volatile("cp.async.wait_group 0;");
    __syncthreads();

    float Ot[16][4];
#pragma unroll
    for (int a = 0; a < 16; a++)
#pragma unroll
        for (int e = 0; e < 4; e++) Ot[a][e] = 0.0f;
    const float snk = sink[h];
    float m0 = snk, m1 = snk, l0 = 1.0f, l1 = 1.0f;

    const int grow0 = qb * 64 + wr * 16 + g;
    const int grow1 = grow0 + 8;
    const int lrow0 = wr * 16 + g;

    for (int kb = 0; kb <= qb; kb++) {
        const int cur = kb & 1;
        const uint32_t kh = KOFF + cur * KPAIR;
        const uint32_t kl = kh + QELE;

        float c[4][4];
#pragma unroll
        for (int a = 0; a < 4; a++)
#pragma unroll
            for (int e = 0; e < 4; e++) c[a][e] = 0.0f;

#pragma unroll 4
        for (int ks = 0; ks < 16; ks++) {
            const int k0 = ks * 16;
            uint32_t aH[4], aL[4];
            ldsm4(sb + (aRow * QSTR + k0 + aCol8) * 2, aH);
            ldsm4(sb + (QELE + aRow * QSTR + k0 + aCol8) * 2, aL);
#pragma unroll
            for (int pair = 0; pair < 2; pair++) {
                const int j0 = wc * 32 + pair * 16;
                uint32_t bH[4], bL[4];
                ldsm4(sb + (kh + (j0 + bRowQK) * QSTR + k0 + bColQK8) * 2, bH);
                ldsm4(sb + (kl + (j0 + bRowQK) * QSTR + k0 + bColQK8) * 2, bL);
#pragma unroll
                for (int s2 = 0; s2 < 2; s2++) {
                    float* cc = c[pair * 2 + s2];
                    mma_bf16(cc, aH, bH + s2 * 2);
                    mma_bf16(cc, aH, bL + s2 * 2);
                    mma_bf16(cc, aL, bH + s2 * 2);
                }
            }
        }

        if (kb < qb) issue_kv(cur ^ 1, kb + 1);
        else asm volatile("cp.async.commit_group;");

        const bool diag = (kb == qb);
#pragma unroll
        for (int a = 0; a < 4; a++) {
            int colb = kb * 64 + wc * 32 + a * 8 + 2 * tc;
            c[a][0] *= SCL; c[a][1] *= SCL; c[a][2] *= SCL; c[a][3] *= SCL;
            if (diag) {
                if (colb     > grow0) c[a][0] = -3.0e38f;
                if (colb + 1 > grow0) c[a][1] = -3.0e38f;
                if (colb     > grow1) c[a][2] = -3.0e38f;
                if (colb + 1 > grow1) c[a][3] = -3.0e38f;
            }
        }

        float tmax0 = -3.0e38f, tmax1 = -3.0e38f;
#pragma unroll
        for (int a = 0; a < 4; a++) {
            tmax0 = fmaxf(tmax0, fmaxf(c[a][0], c[a][1]));
            tmax1 = fmaxf(tmax1, fmaxf(c[a][2], c[a][3]));
        }
        tmax0 = fmaxf(tmax0, __shfl_xor_sync(0xffffffffu, tmax0, 1));
        tmax0 = fmaxf(tmax0, __shfl_xor_sync(0xffffffffu, tmax0, 2));
        tmax1 = fmaxf(tmax1, __shfl_xor_sync(0xffffffffu, tmax1, 1));
        tmax1 = fmaxf(tmax1, __shfl_xor_sync(0xffffffffu, tmax1, 2));
        if (tc == 0) {
            red[0][wc][lrow0] = tmax0;
            red[0][wc][lrow0 + 8] = tmax1;
        }
        __syncthreads();
        float mn0 = fmaxf(m0, fmaxf(red[0][0][lrow0], red[0][1][lrow0]));
        float mn1 = fmaxf(m1, fmaxf(red[0][0][lrow0 + 8], red[0][1][lrow0 + 8]));
        float alpha0 = __expf(m0 - mn0);
        float alpha1 = __expf(m1 - mn1);
#pragma unroll
        for (int a = 0; a < 16; a++) {
            Ot[a][0] *= alpha0; Ot[a][1] *= alpha0;
            Ot[a][2] *= alpha1; Ot[a][3] *= alpha1;
        }
        float tsum0 = 0.0f, tsum1 = 0.0f;
#pragma unroll
        for (int a = 0; a < 4; a++) {
            c[a][0] = __expf(c[a][0] - mn0);
            c[a][1] = __expf(c[a][1] - mn0);
            c[a][2] = __expf(c[a][2] - mn1);
            c[a][3] = __expf(c[a][3] - mn1);
            tsum0 += c[a][0] + c[a][1];
            tsum1 += c[a][2] + c[a][3];
        }
        tsum0 += __shfl_xor_sync(0xffffffffu, tsum0, 1);
        tsum0 += __shfl_xor_sync(0xffffffffu, tsum0, 2);
        tsum1 += __shfl_xor_sync(0xffffffffu, tsum1, 1);
        tsum1 += __shfl_xor_sync(0xffffffffu, tsum1, 2);
        if (tc == 0) {
            red[1][wc][lrow0] = tsum0;
            red[1][wc][lrow0 + 8] = tsum1;
        }
#pragma unroll
        for (int a = 0; a < 4; a++) {
            int cbase = wc * 32 + a * 8 + 2 * tc;
            uint32_t ph, pl;
            split2(c[a][0], c[a][1], ph, pl);
            *(uint32_t*)(smem + POFF + lrow0 * PSTR + cbase) = ph;
            *(uint32_t*)(smem + POFF + PELE + lrow0 * PSTR + cbase) = pl;
            split2(c[a][2], c[a][3], ph, pl);
            *(uint32_t*)(smem + POFF + (lrow0 + 8) * PSTR + cbase) = ph;
            *(uint32_t*)(smem + POFF + PELE + (lrow0 + 8) * PSTR + cbase) = pl;
        }
        __syncthreads();
        l0 = l0 * alpha0 + red[1][0][lrow0] + red[1][1][lrow0];
        l1 = l1 * alpha1 + red[1][0][lrow0 + 8] + red[1][1][lrow0 + 8];
        m0 = mn0; m1 = mn1;

#pragma unroll
        for (int ks = 0; ks < 4; ks++) {
            const int k0 = ks * 16;
            uint32_t pH[4], pL[4];
            ldsm4(sb + (POFF + aRow * PSTR + k0 + aCol8) * 2, pH);
            ldsm4(sb + (POFF + PELE + aRow * PSTR + k0 + aCol8) * 2, pL);
#pragma unroll
            for (int pair = 0; pair < 8; pair++) {
                const int n0 = wc * 128 + pair * 16;
                uint32_t vH[4], vL[4];
                ldsm4t(sb + (kh + (k0 + bRowPV) * QSTR + n0 + bColPV8) * 2, vH);
                ldsm4t(sb + (kl + (k0 + bRowPV) * QSTR + n0 + bColPV8) * 2, vL);
#pragma unroll
                for (int s2 = 0; s2 < 2; s2++) {
                    float* oo = Ot[pair * 2 + s2];
                    mma_bf16(oo, pH, vH + s2 * 2);
                    mma_bf16(oo, pH, vL + s2 * 2);
                    mma_bf16(oo, pL, vH + s2 * 2);
                }
            }
        }
        asm volatile("cp.async.wait_group 0;");
        __syncthreads();
    }

    // epilogue: divide by l, tf32-round (feeds gemm4), write [s][h*256+d]
    const float inv0 = 1.0f / l0, inv1 = 1.0f / l1;
#pragma unroll
    for (int a = 0; a < 16; a++) {
        int col = h * HD + wc * 128 + a * 8 + 2 * tc;
        *(float2*)&qo[(size_t)grow0 * (NH * HD) + col] =
            make_float2(rna_tf32(Ot[a][0] * inv0), rna_tf32(Ot[a][1] * inv0));
        *(float2*)&qo[(size_t)grow1 * (NH * HD) + col] =
            make_float2(rna_tf32(Ot[a][2] * inv1), rna_tf32(Ot[a][3] * inv1));
    }
}

// ---------------- inverse rope on O pe part (in-place, tf32-round) ---------
__global__ void o_rope_inv(float* __restrict__ o, const float* __restrict__ freqs)
{
    const int s = blockIdx.x;
    const int t = threadIdx.x;       // 512
    const int h = t >> 5, i = t & 31;
    float sn, cs;
    sincosf(freqs[s * (RR / 2) + i], &sn, &cs);
    float* p = o + s * (NH * HD) + h * HD + NOPE + 2 * i;
    float x1 = p[0], x2 = p[1];
    p[0] = rna_tf32(fmaf(x1, cs,  x2 * sn));
    p[1] = rna_tf32(fmaf(x2, cs, -x1 * sn));
}

// ---------------- launch ---------------------------------------------------
extern "C" void kernel_launch(void* const* d_in, const int* in_sizes, int n_in,
                              void* d_out, int out_size)
{
    const float* x         = (const float*)d_in[0];
    const float* freqs     = (const float*)d_in[1];
    const float* wq_a      = (const float*)d_in[2];
    const float* q_norm_w  = (const float*)d_in[3];
    const float* wq_b      = (const float*)d_in[4];
    const float* wkv       = (const float*)d_in[5];
    const float* kv_norm_w = (const float*)d_in[6];
    const float* wo_a_w    = (const float*)d_in[7];
    const float* wo_b      = (const float*)d_in[8];
    const float* attn_sink = (const float*)d_in[9];
    float* out = (float*)d_out;

    float *qa, *q, *kvp, *orr, *xr, *wqa, *wqb, *wkvr, *woa, *wob;
    bf16 *kvh, *kvl;
    cudaGetSymbolAddress((void**)&qa,   g_qa);
    cudaGetSymbolAddress((void**)&q,    g_q);
    cudaGetSymbolAddress((void**)&kvp,  g_kvp);
    cudaGetSymbolAddress((void**)&orr,  g_or);
    cudaGetSymbolAddress((void**)&xr,   g_xr);
    cudaGetSymbolAddress((void**)&wqa,  g_wqa);
    cudaGetSymbolAddress((void**)&wqb,  g_wqb);
    cudaGetSymbolAddress((void**)&wkvr, g_wkv);
    cudaGetSymbolAddress((void**)&woa,  g_woa);
    cudaGetSymbolAddress((void**)&wob,  g_wob);
    cudaGetSymbolAddress((void**)&kvh,  g_kvh);
    cudaGetSymbolAddress((void**)&kvl,  g_kvl);

    cudaFuncSetAttribute(gemm_tf32, cudaFuncAttributeMaxDynamicSharedMemorySize, GEMM_SMEM);
    cudaFuncSetAttribute(flash_mma, cudaFuncAttributeMaxDynamicSharedMemorySize, FL_SMEM);

    auto rnd = [&](const float* src, float* dst, int n) {
        int n4 = n / 4;
        round_tf32_vec<<<(n4 + 255) / 256, 256>>>(src, dst, n4);
    };

    rnd(x,    xr,  SS * HIDD);                                       // 0
    rnd(wq_a, wqa, QLAT * HIDD);                                     // 1
    rnd(wq_b, wqb, NH * HD * QLAT);                                  // 2
    // q_a = x @ wq_a^T   [2048,1024]
    gemm_tf32<<<dim3(QLAT / TBN, SS / TBM), 256, GEMM_SMEM>>>(       // 3 <- profiled
        xr, wqa, qa, SS, QLAT, HIDD, HIDD, HIDD, QLAT, 0, 0, 0);
    rmsnorm1024<<<SS, 256>>>(qa, q_norm_w);                          // 4
    // q = rms(q_a) @ wq_b^T   [2048,4096]
    gemm_tf32<<<dim3((NH * HD) / TBN, SS / TBM), 256, GEMM_SMEM>>>(  // 5
        qa, wqb, q, SS, NH * HD, QLAT, QLAT, QLAT, NH * HD, 0, 0, 0);
    rnd(wkv, wkvr, HD * HIDD);                                       // 6
    // kv partials = x @ wkv^T, split-K=4 -> [4][2048,256]
    gemm_tf32<<<dim3(HD / TBN, SS / TBM, KVSPLIT), 256, GEMM_SMEM>>>( // 7
        xr, wkvr, kvp, SS, HD, HIDD, HIDD, HIDD, HD, 0, 0, 0);
    kv_norm_rope<<<SS, 64>>>(kvp, kv_norm_w, freqs, kvh, kvl);       // 8
    // flash attention (fused q-prep) in-place on g_q
    flash_mma<<<dim3(SS / 64, NH), 256, FL_SMEM>>>(q, kvh, kvl, freqs, attn_sink); // 9
    o_rope_inv<<<SS, 512>>>(q, freqs);                               // 10
    rnd(wo_a_w, woa, NG * ORNK * NG * HD);                           // 11
    // o_r = blockdiag(o @ wo_a^T)  [2048,2048], round output (feeds gemm5)
    gemm_tf32<<<dim3((NG * ORNK) / TBN, SS / TBM), 256, GEMM_SMEM>>>( // 12
        q, woa, orr, SS, NG * ORNK, NG * HD, NH * HD, NG * HD, NG * ORNK, ORNK, NG * HD, 1);
    rnd(wo_b, wob, HIDD * NG * ORNK);                                // 13
    // out = o_r @ wo_b^T [2048,2048]
    gemm_tf32<<<dim3(HIDD / TBN, SS / TBM), 256, GEMM_SMEM>>>(       // 14
        orr, wob, out, SS, HIDD, NG * ORNK, NG * ORNK, NG * ORNK, HIDD, 0, 0, 0);
}

// round 13
// speedup vs baseline: 1.0921x; 1.0115x over previous
#include <cuda_runtime.h>
#include <cuda_bf16.h>
#include <math.h>
#include <stdint.h>

#define SS   2048
#define HIDD 2048
#define NH   16
#define HD   256
#define RR   64
#define NOPE 192
#define QLAT 1024
#define ORNK 512
#define NG   4
#define EPSV 1e-6f
#define SCL  0.0625f
#define KVSPLIT 4

typedef __nv_bfloat16 bf16;
typedef __nv_bfloat162 bf162;

// ---------------- scratch (static device globals; no allocations) ----------
__device__ float g_qa[SS * QLAT];
__device__ float g_q [SS * NH * HD];       // q up-proj; flash reads Q / writes O here
__device__ float g_kvp[KVSPLIT * SS * HD]; // kv split-K partials
__device__ float g_or[SS * NG * ORNK];
__device__ bf16 g_kvh[SS * HD], g_kvl[SS * HD];

// integer RNA-to-tf32: bit-identical to cvt.rna.tf32.f32 (no NaN inputs here)
__device__ __forceinline__ uint32_t rna_bits(uint32_t u) {
    return (u + 0x1000u) & 0xFFFFE000u;
}
__device__ __forceinline__ void split2(float x, float y, uint32_t& h, uint32_t& l) {
    bf162 hp, lp;
    hp.x = __float2bfloat16_rn(x);
    hp.y = __float2bfloat16_rn(y);
    lp.x = __float2bfloat16_rn(x - __bfloat162float(hp.x));
    lp.y = __float2bfloat16_rn(y - __bfloat162float(hp.y));
    h = *(uint32_t*)&hp;
    l = *(uint32_t*)&lp;
}
__device__ __forceinline__ uint32_t smem_u32(const void* p) {
    return (uint32_t)__cvta_generic_to_shared(p);
}
__device__ __forceinline__ void ldsm4(uint32_t addr, uint32_t* r) {
    asm volatile("ldmatrix.sync.aligned.m8n8.x4.shared.b16 {%0,%1,%2,%3}, [%4];"
                 : "=r"(r[0]), "=r"(r[1]), "=r"(r[2]), "=r"(r[3]) : "r"(addr));
}
__device__ __forceinline__ void ldsm4t(uint32_t addr, uint32_t* r) {
    asm volatile("ldmatrix.sync.aligned.m8n8.x4.trans.shared.b16 {%0,%1,%2,%3}, [%4];"
                 : "=r"(r[0]), "=r"(r[1]), "=r"(r[2]), "=r"(r[3]) : "r"(addr));
}
__device__ __forceinline__ void mma_bf16(float* d, const uint32_t* a, const uint32_t* b) {
    asm volatile(
        "mma.sync.aligned.m16n8k16.row.col.f32.bf16.bf16.f32 "
        "{%0,%1,%2,%3}, {%4,%5,%6,%7}, {%8,%9}, {%0,%1,%2,%3};"
        : "+f"(d[0]), "+f"(d[1]), "+f"(d[2]), "+f"(d[3])
        : "r"(a[0]), "r"(a[1]), "r"(a[2]), "r"(a[3]), "r"(b[0]), "r"(b[1]));
}

// ---------------- tf32 tensor-core NT GEMM: C = A[M,K] * B[N,K]^T ----------
// operands rounded to tf32 (RNA, integer trick) at fragment load.
#define TBM 128
#define TBN 128
#define TBK 32
#define ASTR 36
#define STG_F ((TBM + TBN) * ASTR)
#define NSTAGE 4
#define GEMM_SMEM (NSTAGE * STG_F * 4)

__global__ __launch_bounds__(256, 1) void gemm_tf32(
    const float* __restrict__ A, const float* __restrict__ B, float* __restrict__ C,
    int M, int N, int K, int lda, int ldb, int ldc,
    int group_n, int group_stride)
{
    extern __shared__ float sm[];
    const int bm0 = blockIdx.y * TBM;
    const int bn0 = blockIdx.x * TBN;
    const int Ksub = K / gridDim.z;
    const int kbase = blockIdx.z * Ksub;
    C += (size_t)blockIdx.z * M * ldc;
    const float* Ap = A + (group_n ? (bn0 / group_n) * (size_t)group_stride : 0);
    const int t = threadIdx.x;
    const int warp = t >> 5, lane = t & 31;
    const int wm = (warp >> 2) * 64, wn = (warp & 3) * 32;
    const int g = lane >> 2, tc = lane & 3;
    const int lrow = t >> 3, lc4 = (t & 7) * 4;

    float acc[4][4][4];
#pragma unroll
    for (int i = 0; i < 4; i++)
#pragma unroll
        for (int j = 0; j < 4; j++)
#pragma unroll
            for (int k = 0; k < 4; k++) acc[i][j][k] = 0.0f;

    const float* Agb = Ap + (size_t)(bm0 + lrow) * lda + kbase + lc4;
    const float* Bgb = B + (size_t)(bn0 + lrow) * ldb + kbase + lc4;

    auto issue = [&](int stage, int k0) {
        float* As = sm + stage * STG_F;
        float* Bs = As + TBM * ASTR;
        uint32_t sa = smem_u32(As + lrow * ASTR + lc4);
        uint32_t sb = smem_u32(Bs + lrow * ASTR + lc4);
        const float* ag = Agb + k0;
        const float* bg = Bgb + k0;
#pragma unroll
        for (int i = 0; i < 4; i++) {
            asm volatile("cp.async.cg.shared.global [%0], [%1], 16;"
                         :: "r"(sa + i * 32 * ASTR * 4), "l"(ag + (size_t)i * 32 * lda));
            asm volatile("cp.async.cg.shared.global [%0], [%1], 16;"
                         :: "r"(sb + i * 32 * ASTR * 4), "l"(bg + (size_t)i * 32 * ldb));
        }
        asm volatile("cp.async.commit_group;");
    };

    auto compute = [&](int stage) {
        const float* As = sm + stage * STG_F;
        const float* Bs = As + TBM * ASTR;
#pragma unroll
        for (int ks = 0; ks < 4; ks++) {
            uint32_t a[4][4], b[4][2];
#pragma unroll
            for (int am = 0; am < 4; am++) {
                const float* ap = As + (wm + am * 16 + g) * ASTR + ks * 8 + tc;
                a[am][0] = rna_bits(__float_as_uint(ap[0]));
                a[am][1] = rna_bits(__float_as_uint(ap[8 * ASTR]));
                a[am][2] = rna_bits(__float_as_uint(ap[4]));
                a[am][3] = rna_bits(__float_as_uint(ap[8 * ASTR + 4]));
            }
#pragma unroll
            for (int bn = 0; bn < 4; bn++) {
                const float* bp = Bs + (wn + bn * 8 + g) * ASTR + ks * 8 + tc;
                b[bn][0] = rna_bits(__float_as_uint(bp[0]));
                b[bn][1] = rna_bits(__float_as_uint(bp[4]));
            }
#pragma unroll
            for (int am = 0; am < 4; am++)
#pragma unroll
                for (int bn = 0; bn < 4; bn++)
                    asm volatile(
                        "mma.sync.aligned.m16n8k8.row.col.f32.tf32.tf32.f32 "
                        "{%0,%1,%2,%3}, {%4,%5,%6,%7}, {%8,%9}, {%0,%1,%2,%3};"
                        : "+f"(acc[am][bn][0]), "+f"(acc[am][bn][1]),
                          "+f"(acc[am][bn][2]), "+f"(acc[am][bn][3])
                        : "r"(a[am][0]), "r"(a[am][1]), "r"(a[am][2]), "r"(a[am][3]),
                          "r"(b[bn][0]), "r"(b[bn][1]));
        }
    };

    const int nk = Ksub / TBK;
    issue(0, 0);
    issue(1, TBK);
    issue(2, 2 * TBK);

    for (int kt = 0; kt < nk; kt++) {
        asm volatile("cp.async.wait_group 2;");
        __syncthreads();
        compute(kt & 3);
        if (kt + 3 < nk) issue((kt + 3) & 3, (kt + 3) * TBK);
        else asm volatile("cp.async.commit_group;");
    }

#pragma unroll
    for (int am = 0; am < 4; am++)
#pragma unroll
        for (int bn = 0; bn < 4; bn++) {
            int row0 = bm0 + wm + am * 16 + g;
            int col = bn0 + wn + bn * 8 + tc * 2;
            *(float2*)&C[(size_t)row0 * ldc + col] =
                make_float2(acc[am][bn][0], acc[am][bn][1]);
            *(float2*)&C[(size_t)(row0 + 8) * ldc + col] =
                make_float2(acc[am][bn][2], acc[am][bn][3]);
        }
}

// ---------------- rmsnorm over 1024 cols (in-place) ------------------------
__global__ void rmsnorm1024(float* __restrict__ x, const float* __restrict__ w)
{
    const int row = blockIdx.x;
    float* xr = x + row * QLAT;
    const int t = threadIdx.x; // 256
    float4 v = ((float4*)xr)[t];
    float ssq = v.x * v.x + v.y * v.y + v.z * v.z + v.w * v.w;
#pragma unroll
    for (int o = 16; o > 0; o >>= 1) ssq += __shfl_xor_sync(0xffffffffu, ssq, o);
    __shared__ float ws[8];
    if ((t & 31) == 0) ws[t >> 5] = ssq;
    __syncthreads();
    float tot = ws[0] + ws[1] + ws[2] + ws[3] + ws[4] + ws[5] + ws[6] + ws[7];
    float sc = rsqrtf(tot / (float)QLAT + EPSV);
    float4 wv = ((const float4*)w)[t];
    v.x *= sc * wv.x; v.y *= sc * wv.y; v.z *= sc * wv.z; v.w *= sc * wv.w;
    ((float4*)xr)[t] = v;
}

// --- kv: sum split-K partials + rmsnorm(256) + rope -> bf16 hi/lo ----------
__global__ void kv_norm_rope(const float* __restrict__ kvp, const float* __restrict__ w,
                             const float* __restrict__ freqs,
                             bf16* __restrict__ kvh, bf16* __restrict__ kvl)
{
    const int s = blockIdx.x;
    const int t = threadIdx.x; // 64
    float4 v = ((const float4*)(kvp + (size_t)s * HD))[t];
#pragma unroll
    for (int z = 1; z < KVSPLIT; z++) {
        float4 p = ((const float4*)(kvp + (size_t)z * SS * HD + (size_t)s * HD))[t];
        v.x += p.x; v.y += p.y; v.z += p.z; v.w += p.w;
    }
    float ssq = v.x * v.x + v.y * v.y + v.z * v.z + v.w * v.w;
#pragma unroll
    for (int o = 16; o > 0; o >>= 1) ssq += __shfl_xor_sync(0xffffffffu, ssq, o);
    __shared__ float ws[2];
    if ((t & 31) == 0) ws[t >> 5] = ssq;
    __syncthreads();
    float sc = rsqrtf((ws[0] + ws[1]) / (float)HD + EPSV);
    float4 wv = ((const float4*)w)[t];
    v.x *= sc * wv.x; v.y *= sc * wv.y; v.z *= sc * wv.z; v.w *= sc * wv.w;
    const int c = t * 4;
    if (c >= NOPE) {
        int i0 = (c - NOPE) >> 1;
        float sn0, cs0, sn1, cs1;
        sincosf(freqs[s * (RR / 2) + i0], &sn0, &cs0);
        sincosf(freqs[s * (RR / 2) + i0 + 1], &sn1, &cs1);
        float x1 = v.x, x2 = v.y;
        v.x = x1 * cs0 - x2 * sn0; v.y = x1 * sn0 + x2 * cs0;
        x1 = v.z; x2 = v.w;
        v.z = x1 * cs1 - x2 * sn1; v.w = x1 * sn1 + x2 * cs1;
    }
    uint32_t h0, l0, h1, l1;
    split2(v.x, v.y, h0, l0);
    split2(v.z, v.w, h1, l1);
    *(uint2*)&kvh[s * HD + c] = make_uint2(h0, h1);
    *(uint2*)&kvl[s * HD + c] = make_uint2(l0, l1);
}

// ============ flash attention via bf16-split mma.sync (K == V) =============
#define QSTR 264
#define PSTR 72
#define QELE (64 * QSTR)
#define KOFF (2 * QELE)
#define KPAIR (2 * QELE)
#define POFF (KOFF + 2 * KPAIR)
#define PELE (64 * PSTR)
#define FL_SMEM ((POFF + 2 * PELE) * 2)

__global__ __launch_bounds__(256, 1) void flash_mma(
    float* __restrict__ qo,
    const bf16* __restrict__ kvh, const bf16* __restrict__ kvl,
    const float* __restrict__ freqs,
    const float* __restrict__ sink)
{
    extern __shared__ __align__(16) bf16 smem[];
    __shared__ float red[2][2][64];

    const int qb = blockIdx.x;
    const int h  = blockIdx.y;
    const int t  = threadIdx.x;
    const int warp = t >> 5, lane = t & 31;
    const int wr = warp >> 1, wc = warp & 1;
    const int g = lane >> 2, tc = lane & 3;

    const uint32_t sb = smem_u32(smem);
    const int aRow = wr * 16 + (lane & 7) + ((lane >> 3) & 1) * 8;
    const int aCol8 = (lane >> 4) * 8;
    const int bRowQK = (lane & 7) + ((lane >> 4) & 1) * 8;
    const int bColQK8 = ((lane >> 3) & 1) * 8;
    const int bRowPV = (lane & 7) + ((lane >> 3) & 1) * 8;
    const int bColPV8 = ((lane >> 4) & 1) * 8;

    auto issue_kv = [&](int stage, int kb) {
        const size_t kbase = (size_t)(kb * 64) * HD;
        uint32_t koff = KOFF + stage * KPAIR;
        for (int i = t; i < 2048; i += 256) {
            int r = i >> 5, cb = i & 31;
            uint32_t dh = sb + (koff + r * QSTR + cb * 8) * 2;
            uint32_t dl = sb + (koff + QELE + r * QSTR + cb * 8) * 2;
            const bf16* srh = kvh + kbase + r * HD + cb * 8;
            const bf16* srl = kvl + kbase + r * HD + cb * 8;
            asm volatile("cp.async.cg.shared.global [%0], [%1], 16;" :: "r"(dh), "l"(srh));
            asm volatile("cp.async.cg.shared.global [%0], [%1], 16;" :: "r"(dl), "l"(srl));
        }
        asm volatile("cp.async.commit_group;");
    };
    issue_kv(0, 0);

    // fused Q prep: per-head rms + rope + hi/lo split -> smem
    {
        const int r = t >> 2, quad = t & 3;
        const int srow = qb * 64 + r;
        const float* qrow = qo + (size_t)srow * (NH * HD) + h * HD + quad * 64;
        float ssq = 0.0f;
#pragma unroll
        for (int j = 0; j < 16; j++) {
            float4 v = ((const float4*)qrow)[j];
            ssq += v.x * v.x + v.y * v.y + v.z * v.z + v.w * v.w;
        }
        ssq += __shfl_xor_sync(0xffffffffu, ssq, 1);
        ssq += __shfl_xor_sync(0xffffffffu, ssq, 2);
        const float sc = rsqrtf(ssq / (float)HD + EPSV);
        const bool pe = (quad == 3);
#pragma unroll
        for (int j = 0; j < 16; j++) {
            float4 v = ((const float4*)qrow)[j];
            v.x *= sc; v.y *= sc; v.z *= sc; v.w *= sc;
            if (pe) {
                float sn, cs, x1, x2;
                sincosf(freqs[srow * (RR / 2) + 2 * j], &sn, &cs);
                x1 = v.x; x2 = v.y; v.x = x1 * cs - x2 * sn; v.y = x1 * sn + x2 * cs;
                sincosf(freqs[srow * (RR / 2) + 2 * j + 1], &sn, &cs);
                x1 = v.z; x2 = v.w; v.z = x1 * cs - x2 * sn; v.w = x1 * sn + x2 * cs;
            }
            uint32_t h0, l0, h1, l1;
            split2(v.x, v.y, h0, l0);
            split2(v.z, v.w, h1, l1);
            const int d = quad * 64 + j * 4;
            *(uint2*)(smem + r * QSTR + d) = make_uint2(h0, h1);
            *(uint2*)(smem + QELE + r * QSTR + d) = make_uint2(l0, l1);
        }
    }
    asm volatile("cp.async.wait_group 0;");
    __syncthreads();

    float Ot[16][4];
#pragma unroll
    for (int a = 0; a < 16; a++)
#pragma unroll
        for (int e = 0; e < 4; e++) Ot[a][e] = 0.0f;
    const float snk = sink[h];
    float m0 = snk, m1 = snk, l0 = 1.0f, l1 = 1.0f;

    const int grow0 = qb * 64 + wr * 16 + g;
    const int grow1 = grow0 + 8;
    const int lrow0 = wr * 16 + g;

    for (int kb = 0; kb <= qb; kb++) {
        const int cur = kb & 1;
        const uint32_t kh = KOFF + cur * KPAIR;
        const uint32_t kl = kh + QELE;

        float c[4][4];
#pragma unroll
        for (int a = 0; a < 4; a++)
#pragma unroll
            for (int e = 0; e < 4; e++) c[a][e] = 0.0f;

#pragma unroll 4
        for (int ks = 0; ks < 16; ks++) {
            const int k0 = ks * 16;
            uint32_t aH[4], aL[4];
            ldsm4(sb + (aRow * QSTR + k0 + aCol8) * 2, aH);
            ldsm4(sb + (QELE + aRow * QSTR + k0 + aCol8) * 2, aL);
#pragma unroll
            for (int pair = 0; pair < 2; pair++) {
                const int j0 = wc * 32 + pair * 16;
                uint32_t bH[4], bL[4];
                ldsm4(sb + (kh + (j0 + bRowQK) * QSTR + k0 + bColQK8) * 2, bH);
                ldsm4(sb + (kl + (j0 + bRowQK) * QSTR + k0 + bColQK8) * 2, bL);
#pragma unroll
                for (int s2 = 0; s2 < 2; s2++) {
                    float* cc = c[pair * 2 + s2];
                    mma_bf16(cc, aH, bH + s2 * 2);
                    mma_bf16(cc, aH, bL + s2 * 2);
                    mma_bf16(cc, aL, bH + s2 * 2);
                }
            }
        }

        if (kb < qb) issue_kv(cur ^ 1, kb + 1);
        else asm volatile("cp.async.commit_group;");

        const bool diag = (kb == qb);
#pragma unroll
        for (int a = 0; a < 4; a++) {
            int colb = kb * 64 + wc * 32 + a * 8 + 2 * tc;
            c[a][0] *= SCL; c[a][1] *= SCL; c[a][2] *= SCL; c[a][3] *= SCL;
            if (diag) {
                if (colb     > grow0) c[a][0] = -3.0e38f;
                if (colb + 1 > grow0) c[a][1] = -3.0e38f;
                if (colb     > grow1) c[a][2] = -3.0e38f;
                if (colb + 1 > grow1) c[a][3] = -3.0e38f;
            }
        }

        float tmax0 = -3.0e38f, tmax1 = -3.0e38f;
#pragma unroll
        for (int a = 0; a < 4; a++) {
            tmax0 = fmaxf(tmax0, fmaxf(c[a][0], c[a][1]));
            tmax1 = fmaxf(tmax1, fmaxf(c[a][2], c[a][3]));
        }
        tmax0 = fmaxf(tmax0, __shfl_xor_sync(0xffffffffu, tmax0, 1));
        tmax0 = fmaxf(tmax0, __shfl_xor_sync(0xffffffffu, tmax0, 2));
        tmax1 = fmaxf(tmax1, __shfl_xor_sync(0xffffffffu, tmax1, 1));
        tmax1 = fmaxf(tmax1, __shfl_xor_sync(0xffffffffu, tmax1, 2));
        if (tc == 0) {
            red[0][wc][lrow0] = tmax0;
            red[0][wc][lrow0 + 8] = tmax1;
        }
        __syncthreads();
        float mn0 = fmaxf(m0, fmaxf(red[0][0][lrow0], red[0][1][lrow0]));
        float mn1 = fmaxf(m1, fmaxf(red[0][0][lrow0 + 8], red[0][1][lrow0 + 8]));
        float alpha0 = __expf(m0 - mn0);
        float alpha1 = __expf(m1 - mn1);
#pragma unroll
        for (int a = 0; a < 16; a++) {
            Ot[a][0] *= alpha0; Ot[a][1] *= alpha0;
            Ot[a][2] *= alpha1; Ot[a][3] *= alpha1;
        }
        float tsum0 = 0.0f, tsum1 = 0.0f;
#pragma unroll
        for (int a = 0; a < 4; a++) {
            c[a][0] = __expf(c[a][0] - mn0);
            c[a][1] = __expf(c[a][1] - mn0);
            c[a][2] = __expf(c[a][2] - mn1);
            c[a][3] = __expf(c[a][3] - mn1);
            tsum0 += c[a][0] + c[a][1];
            tsum1 += c[a][2] + c[a][3];
        }
        tsum0 += __shfl_xor_sync(0xffffffffu, tsum0, 1);
        tsum0 += __shfl_xor_sync(0xffffffffu, tsum0, 2);
        tsum1 += __shfl_xor_sync(0xffffffffu, tsum1, 1);
        tsum1 += __shfl_xor_sync(0xffffffffu, tsum1, 2);
        if (tc == 0) {
            red[1][wc][lrow0] = tsum0;
            red[1][wc][lrow0 + 8] = tsum1;
        }
#pragma unroll
        for (int a = 0; a < 4; a++) {
            int cbase = wc * 32 + a * 8 + 2 * tc;
            uint32_t ph, pl;
            split2(c[a][0], c[a][1], ph, pl);
            *(uint32_t*)(smem + POFF + lrow0 * PSTR + cbase) = ph;
            *(uint32_t*)(smem + POFF + PELE + lrow0 * PSTR + cbase) = pl;
            split2(c[a][2], c[a][3], ph, pl);
            *(uint32_t*)(smem + POFF + (lrow0 + 8) * PSTR + cbase) = ph;
            *(uint32_t*)(smem + POFF + PELE + (lrow0 + 8) * PSTR + cbase) = pl;
        }
        __syncthreads();
        l0 = l0 * alpha0 + red[1][0][lrow0] + red[1][1][lrow0];
        l1 = l1 * alpha1 + red[1][0][lrow0 + 8] + red[1][1][lrow0 + 8];
        m0 = mn0; m1 = mn1;

#pragma unroll
        for (int ks = 0; ks < 4; ks++) {
            const int k0 = ks * 16;
            uint32_t pH[4], pL[4];
            ldsm4(sb + (POFF + aRow * PSTR + k0 + aCol8) * 2, pH);
            ldsm4(sb + (POFF + PELE + aRow * PSTR + k0 + aCol8) * 2, pL);
#pragma unroll
            for (int pair = 0; pair < 8; pair++) {
                const int n0 = wc * 128 + pair * 16;
                uint32_t vH[4], vL[4];
                ldsm4t(sb + (kh + (k0 + bRowPV) * QSTR + n0 + bColPV8) * 2, vH);
                ldsm4t(sb + (kl + (k0 + bRowPV) * QSTR + n0 + bColPV8) * 2, vL);
#pragma unroll
                for (int s2 = 0; s2 < 2; s2++) {
                    float* oo = Ot[pair * 2 + s2];
                    mma_bf16(oo, pH, vH + s2 * 2);
                    mma_bf16(oo, pH, vL + s2 * 2);
                    mma_bf16(oo, pL, vH + s2 * 2);
                }
            }
        }
        asm volatile("cp.async.wait_group 0;");
        __syncthreads();
    }

    // epilogue: divide by l, write [s][h*256+d]
    const float inv0 = 1.0f / l0, inv1 = 1.0f / l1;
#pragma unroll
    for (int a = 0; a < 16; a++) {
        int col = h * HD + wc * 128 + a * 8 + 2 * tc;
        *(float2*)&qo[(size_t)grow0 * (NH * HD) + col] =
            make_float2(Ot[a][0] * inv0, Ot[a][1] * inv0);
        *(float2*)&qo[(size_t)grow1 * (NH * HD) + col] =
            make_float2(Ot[a][2] * inv1, Ot[a][3] * inv1);
    }
}

// ---------------- inverse rope on O pe part (in-place) ---------------------
__global__ void o_rope_inv(float* __restrict__ o, const float* __restrict__ freqs)
{
    const int s = blockIdx.x;
    const int t = threadIdx.x;       // 512
    const int h = t >> 5, i = t & 31;
    float sn, cs;
    sincosf(freqs[s * (RR / 2) + i], &sn, &cs);
    float* p = o + s * (NH * HD) + h * HD + NOPE + 2 * i;
    float x1 = p[0], x2 = p[1];
    p[0] = fmaf(x1, cs,  x2 * sn);
    p[1] = fmaf(x2, cs, -x1 * sn);
}

// ---------------- launch ---------------------------------------------------
extern "C" void kernel_launch(void* const* d_in, const int* in_sizes, int n_in,
                              void* d_out, int out_size)
{
    const float* x         = (const float*)d_in[0];
    const float* freqs     = (const float*)d_in[1];
    const float* wq_a      = (const float*)d_in[2];
    const float* q_norm_w  = (const float*)d_in[3];
    const float* wq_b      = (const float*)d_in[4];
    const float* wkv       = (const float*)d_in[5];
    const float* kv_norm_w = (const float*)d_in[6];
    const float* wo_a_w    = (const float*)d_in[7];
    const float* wo_b      = (const float*)d_in[8];
    const float* attn_sink = (const float*)d_in[9];
    float* out = (float*)d_out;

    float *qa, *q, *kvp, *orr;
    bf16 *kvh, *kvl;
    cudaGetSymbolAddress((void**)&qa,  g_qa);
    cudaGetSymbolAddress((void**)&q,   g_q);
    cudaGetSymbolAddress((void**)&kvp, g_kvp);
    cudaGetSymbolAddress((void**)&orr, g_or);
    cudaGetSymbolAddress((void**)&kvh, g_kvh);
    cudaGetSymbolAddress((void**)&kvl, g_kvl);

    cudaFuncSetAttribute(gemm_tf32, cudaFuncAttributeMaxDynamicSharedMemorySize, GEMM_SMEM);
    cudaFuncSetAttribute(flash_mma, cudaFuncAttributeMaxDynamicSharedMemorySize, FL_SMEM);

    // q_a = x @ wq_a^T   [2048,1024]
    gemm_tf32<<<dim3(QLAT / TBN, SS / TBM), 256, GEMM_SMEM>>>(       // 0
        x, wq_a, qa, SS, QLAT, HIDD, HIDD, HIDD, QLAT, 0, 0);
    rmsnorm1024<<<SS, 256>>>(qa, q_norm_w);                          // 1
    // q = rms(q_a) @ wq_b^T   [2048,4096]
    gemm_tf32<<<dim3((NH * HD) / TBN, SS / TBM), 256, GEMM_SMEM>>>(  // 2
        qa, wq_b, q, SS, NH * HD, QLAT, QLAT, QLAT, NH * HD, 0, 0);
    // kv partials = x @ wkv^T, split-K=4 -> [4][2048,256]
    gemm_tf32<<<dim3(HD / TBN, SS / TBM, KVSPLIT), 256, GEMM_SMEM>>>( // 3 <- profiled
        x, wkv, kvp, SS, HD, HIDD, HIDD, HIDD, HD, 0, 0);
    kv_norm_rope<<<SS, 64>>>(kvp, kv_norm_w, freqs, kvh, kvl);       // 4
    // flash attention (fused q-prep) in-place on g_q
    flash_mma<<<dim3(SS / 64, NH), 256, FL_SMEM>>>(q, kvh, kvl, freqs, attn_sink); // 5
    o_rope_inv<<<SS, 512>>>(q, freqs);                               // 6
    // o_r = blockdiag(o @ wo_a^T)  [2048,2048]
    gemm_tf32<<<dim3((NG * ORNK) / TBN, SS / TBM), 256, GEMM_SMEM>>>( // 7
        q, wo_a_w, orr, SS, NG * ORNK, NG * HD, NH * HD, NG * HD, NG * ORNK, ORNK, NG * HD);
    // out = o_r @ wo_b^T [2048,2048]
    gemm_tf32<<<dim3(HIDD / TBN, SS / TBM), 256, GEMM_SMEM>>>(       // 8
        orr, wo_b, out, SS, HIDD, NG * ORNK, NG * ORNK, NG * ORNK, HIDD, 0, 0);
}

// round 14
// speedup vs baseline: 1.1837x; 1.0838x over previous
#include <cuda_runtime.h>
#include <cuda_bf16.h>
#include <math.h>
#include <stdint.h>

#define SS   2048
#define HIDD 2048
#define NH   16
#define HD   256
#define RR   64
#define NOPE 192
#define QLAT 1024
#define ORNK 512
#define NG   4
#define EPSV 1e-6f
#define SCL  0.0625f
#define KVSPLIT 4

typedef __nv_bfloat16 bf16;
typedef __nv_bfloat162 bf162;

// ---------------- scratch (static device globals; no allocations) ----------
__device__ float g_qa[SS * QLAT];
__device__ float g_q [SS * NH * HD];       // q up-proj; flash reads Q / writes O here
__device__ float g_kvp[KVSPLIT * SS * HD]; // kv split-K partials
__device__ float g_or[SS * NG * ORNK];
__device__ bf16 g_kvh[SS * HD], g_kvl[SS * HD];

// integer RNA-to-tf32: bit-identical to cvt.rna.tf32.f32 (no NaN inputs here)
__device__ __forceinline__ uint32_t rna_bits(uint32_t u) {
    return (u + 0x1000u) & 0xFFFFE000u;
}
__device__ __forceinline__ void split2(float x, float y, uint32_t& h, uint32_t& l) {
    bf162 hp, lp;
    hp.x = __float2bfloat16_rn(x);
    hp.y = __float2bfloat16_rn(y);
    lp.x = __float2bfloat16_rn(x - __bfloat162float(hp.x));
    lp.y = __float2bfloat16_rn(y - __bfloat162float(hp.y));
    h = *(uint32_t*)&hp;
    l = *(uint32_t*)&lp;
}
__device__ __forceinline__ uint32_t smem_u32(const void* p) {
    return (uint32_t)__cvta_generic_to_shared(p);
}
__device__ __forceinline__ void ldsm4(uint32_t addr, uint32_t* r) {
    asm volatile("ldmatrix.sync.aligned.m8n8.x4.shared.b16 {%0,%1,%2,%3}, [%4];"
                 : "=r"(r[0]), "=r"(r[1]), "=r"(r[2]), "=r"(r[3]) : "r"(addr));
}
__device__ __forceinline__ void ldsm4t(uint32_t addr, uint32_t* r) {
    asm volatile("ldmatrix.sync.aligned.m8n8.x4.trans.shared.b16 {%0,%1,%2,%3}, [%4];"
                 : "=r"(r[0]), "=r"(r[1]), "=r"(r[2]), "=r"(r[3]) : "r"(addr));
}
__device__ __forceinline__ void mma_bf16(float* d, const uint32_t* a, const uint32_t* b) {
    asm volatile(
        "mma.sync.aligned.m16n8k16.row.col.f32.bf16.bf16.f32 "
        "{%0,%1,%2,%3}, {%4,%5,%6,%7}, {%8,%9}, {%0,%1,%2,%3};"
        : "+f"(d[0]), "+f"(d[1]), "+f"(d[2]), "+f"(d[3])
        : "r"(a[0]), "r"(a[1]), "r"(a[2]), "r"(a[3]), "r"(b[0]), "r"(b[1]));
}

// ---------------- tf32 tensor-core NT GEMM: C = A[M,K] * B[N,K]^T ----------
// 3-stage cp.async pipeline, 2 CTAs/SM for latency hiding.
#define TBM 128
#define TBN 128
#define TBK 32
#define ASTR 36
#define STG_F ((TBM + TBN) * ASTR)
#define NSTAGE 3
#define GEMM_SMEM (NSTAGE * STG_F * 4)   // 110592 bytes

__global__ __launch_bounds__(256, 2) void gemm_tf32(
    const float* __restrict__ A, const float* __restrict__ B, float* __restrict__ C,
    int M, int N, int K, int lda, int ldb, int ldc,
    int group_n, int group_stride)
{
    extern __shared__ float sm[];
    const int bm0 = blockIdx.y * TBM;
    const int bn0 = blockIdx.x * TBN;
    const int Ksub = K / gridDim.z;
    const int kbase = blockIdx.z * Ksub;
    C += (size_t)blockIdx.z * M * ldc;
    const float* Ap = A + (group_n ? (bn0 / group_n) * (size_t)group_stride : 0);
    const int t = threadIdx.x;
    const int warp = t >> 5, lane = t & 31;
    const int wm = (warp >> 2) * 64, wn = (warp & 3) * 32;
    const int g = lane >> 2, tc = lane & 3;
    const int lrow = t >> 3, lc4 = (t & 7) * 4;

    float acc[4][4][4];
#pragma unroll
    for (int i = 0; i < 4; i++)
#pragma unroll
        for (int j = 0; j < 4; j++)
#pragma unroll
            for (int k = 0; k < 4; k++) acc[i][j][k] = 0.0f;

    const float* Agb = Ap + (size_t)(bm0 + lrow) * lda + kbase + lc4;
    const float* Bgb = B + (size_t)(bn0 + lrow) * ldb + kbase + lc4;

    auto issue = [&](int stage, int k0) {
        float* As = sm + stage * STG_F;
        float* Bs = As + TBM * ASTR;
        uint32_t sa = smem_u32(As + lrow * ASTR + lc4);
        uint32_t sb = smem_u32(Bs + lrow * ASTR + lc4);
        const float* ag = Agb + k0;
        const float* bg = Bgb + k0;
#pragma unroll
        for (int i = 0; i < 4; i++) {
            asm volatile("cp.async.cg.shared.global [%0], [%1], 16;"
                         :: "r"(sa + i * 32 * ASTR * 4), "l"(ag + (size_t)i * 32 * lda));
            asm volatile("cp.async.cg.shared.global [%0], [%1], 16;"
                         :: "r"(sb + i * 32 * ASTR * 4), "l"(bg + (size_t)i * 32 * ldb));
        }
        asm volatile("cp.async.commit_group;");
    };

    auto compute = [&](int stage) {
        const float* As = sm + stage * STG_F;
        const float* Bs = As + TBM * ASTR;
#pragma unroll
        for (int ks = 0; ks < 4; ks++) {
            uint32_t a[4][4], b[4][2];
#pragma unroll
            for (int am = 0; am < 4; am++) {
                const float* ap = As + (wm + am * 16 + g) * ASTR + ks * 8 + tc;
                a[am][0] = rna_bits(__float_as_uint(ap[0]));
                a[am][1] = rna_bits(__float_as_uint(ap[8 * ASTR]));
                a[am][2] = rna_bits(__float_as_uint(ap[4]));
                a[am][3] = rna_bits(__float_as_uint(ap[8 * ASTR + 4]));
            }
#pragma unroll
            for (int bn = 0; bn < 4; bn++) {
                const float* bp = Bs + (wn + bn * 8 + g) * ASTR + ks * 8 + tc;
                b[bn][0] = rna_bits(__float_as_uint(bp[0]));
                b[bn][1] = rna_bits(__float_as_uint(bp[4]));
            }
#pragma unroll
            for (int am = 0; am < 4; am++)
#pragma unroll
                for (int bn = 0; bn < 4; bn++)
                    asm volatile(
                        "mma.sync.aligned.m16n8k8.row.col.f32.tf32.tf32.f32 "
                        "{%0,%1,%2,%3}, {%4,%5,%6,%7}, {%8,%9}, {%0,%1,%2,%3};"
                        : "+f"(acc[am][bn][0]), "+f"(acc[am][bn][1]),
                          "+f"(acc[am][bn][2]), "+f"(acc[am][bn][3])
                        : "r"(a[am][0]), "r"(a[am][1]), "r"(a[am][2]), "r"(a[am][3]),
                          "r"(b[bn][0]), "r"(b[bn][1]));
        }
    };

    const int nk = Ksub / TBK;   // >= 16 for all uses
    issue(0, 0);
    issue(1, TBK);

    for (int kt = 0; kt < nk; kt++) {
        asm volatile("cp.async.wait_group 1;");
        __syncthreads();
        compute(kt % 3);
        if (kt + 2 < nk) issue((kt + 2) % 3, (kt + 2) * TBK);
        else asm volatile("cp.async.commit_group;");
    }

#pragma unroll
    for (int am = 0; am < 4; am++)
#pragma unroll
        for (int bn = 0; bn < 4; bn++) {
            int row0 = bm0 + wm + am * 16 + g;
            int col = bn0 + wn + bn * 8 + tc * 2;
            *(float2*)&C[(size_t)row0 * ldc + col] =
                make_float2(acc[am][bn][0], acc[am][bn][1]);
            *(float2*)&C[(size_t)(row0 + 8) * ldc + col] =
                make_float2(acc[am][bn][2], acc[am][bn][3]);
        }
}

// ---------------- rmsnorm over 1024 cols (in-place) ------------------------
__global__ void rmsnorm1024(float* __restrict__ x, const float* __restrict__ w)
{
    const int row = blockIdx.x;
    float* xr = x + row * QLAT;
    const int t = threadIdx.x; // 256
    float4 v = ((float4*)xr)[t];
    float ssq = v.x * v.x + v.y * v.y + v.z * v.z + v.w * v.w;
#pragma unroll
    for (int o = 16; o > 0; o >>= 1) ssq += __shfl_xor_sync(0xffffffffu, ssq, o);
    __shared__ float ws[8];
    if ((t & 31) == 0) ws[t >> 5] = ssq;
    __syncthreads();
    float tot = ws[0] + ws[1] + ws[2] + ws[3] + ws[4] + ws[5] + ws[6] + ws[7];
    float sc = rsqrtf(tot / (float)QLAT + EPSV);
    float4 wv = ((const float4*)w)[t];
    v.x *= sc * wv.x; v.y *= sc * wv.y; v.z *= sc * wv.z; v.w *= sc * wv.w;
    ((float4*)xr)[t] = v;
}

// --- kv: sum split-K partials + rmsnorm(256) + rope -> bf16 hi/lo ----------
__global__ void kv_norm_rope(const float* __restrict__ kvp, const float* __restrict__ w,
                             const float* __restrict__ freqs,
                             bf16* __restrict__ kvh, bf16* __restrict__ kvl)
{
    const int s = blockIdx.x;
    const int t = threadIdx.x; // 64
    float4 v = ((const float4*)(kvp + (size_t)s * HD))[t];
#pragma unroll
    for (int z = 1; z < KVSPLIT; z++) {
        float4 p = ((const float4*)(kvp + (size_t)z * SS * HD + (size_t)s * HD))[t];
        v.x += p.x; v.y += p.y; v.z += p.z; v.w += p.w;
    }
    float ssq = v.x * v.x + v.y * v.y + v.z * v.z + v.w * v.w;
#pragma unroll
    for (int o = 16; o > 0; o >>= 1) ssq += __shfl_xor_sync(0xffffffffu, ssq, o);
    __shared__ float ws[2];
    if ((t & 31) == 0) ws[t >> 5] = ssq;
    __syncthreads();
    float sc = rsqrtf((ws[0] + ws[1]) / (float)HD + EPSV);
    float4 wv = ((const float4*)w)[t];
    v.x *= sc * wv.x; v.y *= sc * wv.y; v.z *= sc * wv.z; v.w *= sc * wv.w;
    const int c = t * 4;
    if (c >= NOPE) {
        int i0 = (c - NOPE) >> 1;
        float sn0, cs0, sn1, cs1;
        sincosf(freqs[s * (RR / 2) + i0], &sn0, &cs0);
        sincosf(freqs[s * (RR / 2) + i0 + 1], &sn1, &cs1);
        float x1 = v.x, x2 = v.y;
        v.x = x1 * cs0 - x2 * sn0; v.y = x1 * sn0 + x2 * cs0;
        x1 = v.z; x2 = v.w;
        v.z = x1 * cs1 - x2 * sn1; v.w = x1 * sn1 + x2 * cs1;
    }
    uint32_t h0, l0, h1, l1;
    split2(v.x, v.y, h0, l0);
    split2(v.z, v.w, h1, l1);
    *(uint2*)&kvh[s * HD + c] = make_uint2(h0, h1);
    *(uint2*)&kvl[s * HD + c] = make_uint2(l0, l1);
}

// ============ flash attention via bf16-split mma.sync (K == V) =============
#define QSTR 264
#define PSTR 72
#define QELE (64 * QSTR)
#define KOFF (2 * QELE)
#define KPAIR (2 * QELE)
#define POFF (KOFF + 2 * KPAIR)
#define PELE (64 * PSTR)
#define FL_SMEM ((POFF + 2 * PELE) * 2)

__global__ __launch_bounds__(256, 1) void flash_mma(
    float* __restrict__ qo,
    const bf16* __restrict__ kvh, const bf16* __restrict__ kvl,
    const float* __restrict__ freqs,
    const float* __restrict__ sink)
{
    extern __shared__ __align__(16) bf16 smem[];
    __shared__ float red[2][2][64];

    const int qb = blockIdx.x;
    const int h  = blockIdx.y;
    const int t  = threadIdx.x;
    const int warp = t >> 5, lane = t & 31;
    const int wr = warp >> 1, wc = warp & 1;
    const int g = lane >> 2, tc = lane & 3;

    const uint32_t sb = smem_u32(smem);
    const int aRow = wr * 16 + (lane & 7) + ((lane >> 3) & 1) * 8;
    const int aCol8 = (lane >> 4) * 8;
    const int bRowQK = (lane & 7) + ((lane >> 4) & 1) * 8;
    const int bColQK8 = ((lane >> 3) & 1) * 8;
    const int bRowPV = (lane & 7) + ((lane >> 3) & 1) * 8;
    const int bColPV8 = ((lane >> 4) & 1) * 8;

    auto issue_kv = [&](int stage, int kb) {
        const size_t kbase = (size_t)(kb * 64) * HD;
        uint32_t koff = KOFF + stage * KPAIR;
        for (int i = t; i < 2048; i += 256) {
            int r = i >> 5, cb = i & 31;
            uint32_t dh = sb + (koff + r * QSTR + cb * 8) * 2;
            uint32_t dl = sb + (koff + QELE + r * QSTR + cb * 8) * 2;
            const bf16* srh = kvh + kbase + r * HD + cb * 8;
            const bf16* srl = kvl + kbase + r * HD + cb * 8;
            asm volatile("cp.async.cg.shared.global [%0], [%1], 16;" :: "r"(dh), "l"(srh));
            asm volatile("cp.async.cg.shared.global [%0], [%1], 16;" :: "r"(dl), "l"(srl));
        }
        asm volatile("cp.async.commit_group;");
    };
    issue_kv(0, 0);

    // fused Q prep: per-head rms + rope + hi/lo split -> smem
    {
        const int r = t >> 2, quad = t & 3;
        const int srow = qb * 64 + r;
        const float* qrow = qo + (size_t)srow * (NH * HD) + h * HD + quad * 64;
        float ssq = 0.0f;
#pragma unroll
        for (int j = 0; j < 16; j++) {
            float4 v = ((const float4*)qrow)[j];
            ssq += v.x * v.x + v.y * v.y + v.z * v.z + v.w * v.w;
        }
        ssq += __shfl_xor_sync(0xffffffffu, ssq, 1);
        ssq += __shfl_xor_sync(0xffffffffu, ssq, 2);
        const float sc = rsqrtf(ssq / (float)HD + EPSV);
        const bool pe = (quad == 3);
#pragma unroll
        for (int j = 0; j < 16; j++) {
            float4 v = ((const float4*)qrow)[j];
            v.x *= sc; v.y *= sc; v.z *= sc; v.w *= sc;
            if (pe) {
                float sn, cs, x1, x2;
                sincosf(freqs[srow * (RR / 2) + 2 * j], &sn, &cs);
                x1 = v.x; x2 = v.y; v.x = x1 * cs - x2 * sn; v.y = x1 * sn + x2 * cs;
                sincosf(freqs[srow * (RR / 2) + 2 * j + 1], &sn, &cs);
                x1 = v.z; x2 = v.w; v.z = x1 * cs - x2 * sn; v.w = x1 * sn + x2 * cs;
            }
            uint32_t h0, l0, h1, l1;
            split2(v.x, v.y, h0, l0);
            split2(v.z, v.w, h1, l1);
            const int d = quad * 64 + j * 4;
            *(uint2*)(smem + r * QSTR + d) = make_uint2(h0, h1);
            *(uint2*)(smem + QELE + r * QSTR + d) = make_uint2(l0, l1);
        }
    }
    asm volatile("cp.async.wait_group 0;");
    __syncthreads();

    float Ot[16][4];
#pragma unroll
    for (int a = 0; a < 16; a++)
#pragma unroll
        for (int e = 0; e < 4; e++) Ot[a][e] = 0.0f;
    const float snk = sink[h];
    float m0 = snk, m1 = snk, l0 = 1.0f, l1 = 1.0f;

    const int grow0 = qb * 64 + wr * 16 + g;
    const int grow1 = grow0 + 8;
    const int lrow0 = wr * 16 + g;

    for (int kb = 0; kb <= qb; kb++) {
        const int cur = kb & 1;
        const uint32_t kh = KOFF + cur * KPAIR;
        const uint32_t kl = kh + QELE;

        float c[4][4];
#pragma unroll
        for (int a = 0; a < 4; a++)
#pragma unroll
            for (int e = 0; e < 4; e++) c[a][e] = 0.0f;

#pragma unroll 4
        for (int ks = 0; ks < 16; ks++) {
            const int k0 = ks * 16;
            uint32_t aH[4], aL[4];
            ldsm4(sb + (aRow * QSTR + k0 + aCol8) * 2, aH);
            ldsm4(sb + (QELE + aRow * QSTR + k0 + aCol8) * 2, aL);
#pragma unroll
            for (int pair = 0; pair < 2; pair++) {
                const int j0 = wc * 32 + pair * 16;
                uint32_t bH[4], bL[4];
                ldsm4(sb + (kh + (j0 + bRowQK) * QSTR + k0 + bColQK8) * 2, bH);
                ldsm4(sb + (kl + (j0 + bRowQK) * QSTR + k0 + bColQK8) * 2, bL);
#pragma unroll
                for (int s2 = 0; s2 < 2; s2++) {
                    float* cc = c[pair * 2 + s2];
                    mma_bf16(cc, aH, bH + s2 * 2);
                    mma_bf16(cc, aH, bL + s2 * 2);
                    mma_bf16(cc, aL, bH + s2 * 2);
                }
            }
        }

        if (kb < qb) issue_kv(cur ^ 1, kb + 1);
        else asm volatile("cp.async.commit_group;");

        const bool diag = (kb == qb);
#pragma unroll
        for (int a = 0; a < 4; a++) {
            int colb = kb * 64 + wc * 32 + a * 8 + 2 * tc;
            c[a][0] *= SCL; c[a][1] *= SCL; c[a][2] *= SCL; c[a][3] *= SCL;
            if (diag) {
                if (colb     > grow0) c[a][0] = -3.0e38f;
                if (colb + 1 > grow0) c[a][1] = -3.0e38f;
                if (colb     > grow1) c[a][2] = -3.0e38f;
                if (colb + 1 > grow1) c[a][3] = -3.0e38f;
            }
        }

        float tmax0 = -3.0e38f, tmax1 = -3.0e38f;
#pragma unroll
        for (int a = 0; a < 4; a++) {
            tmax0 = fmaxf(tmax0, fmaxf(c[a][0], c[a][1]));
            tmax1 = fmaxf(tmax1, fmaxf(c[a][2], c[a][3]));
        }
        tmax0 = fmaxf(tmax0, __shfl_xor_sync(0xffffffffu, tmax0, 1));
        tmax0 = fmaxf(tmax0, __shfl_xor_sync(0xffffffffu, tmax0, 2));
        tmax1 = fmaxf(tmax1, __shfl_xor_sync(0xffffffffu, tmax1, 1));
        tmax1 = fmaxf(tmax1, __shfl_xor_sync(0xffffffffu, tmax1, 2));
        if (tc == 0) {
            red[0][wc][lrow0] = tmax0;
            red[0][wc][lrow0 + 8] = tmax1;
        }
        __syncthreads();
        float mn0 = fmaxf(m0, fmaxf(red[0][0][lrow0], red[0][1][lrow0]));
        float mn1 = fmaxf(m1, fmaxf(red[0][0][lrow0 + 8], red[0][1][lrow0 + 8]));
        float alpha0 = __expf(m0 - mn0);
        float alpha1 = __expf(m1 - mn1);
#pragma unroll
        for (int a = 0; a < 16; a++) {
            Ot[a][0] *= alpha0; Ot[a][1] *= alpha0;
            Ot[a][2] *= alpha1; Ot[a][3] *= alpha1;
        }
        float tsum0 = 0.0f, tsum1 = 0.0f;
#pragma unroll
        for (int a = 0; a < 4; a++) {
            c[a][0] = __expf(c[a][0] - mn0);
            c[a][1] = __expf(c[a][1] - mn0);
            c[a][2] = __expf(c[a][2] - mn1);
            c[a][3] = __expf(c[a][3] - mn1);
            tsum0 += c[a][0] + c[a][1];
            tsum1 += c[a][2] + c[a][3];
        }
        tsum0 += __shfl_xor_sync(0xffffffffu, tsum0, 1);
        tsum0 += __shfl_xor_sync(0xffffffffu, tsum0, 2);
        tsum1 += __shfl_xor_sync(0xffffffffu, tsum1, 1);
        tsum1 += __shfl_xor_sync(0xffffffffu, tsum1, 2);
        if (tc == 0) {
            red[1][wc][lrow0] = tsum0;
            red[1][wc][lrow0 + 8] = tsum1;
        }
#pragma unroll
        for (int a = 0; a < 4; a++) {
            int cbase = wc * 32 + a * 8 + 2 * tc;
            uint32_t ph, pl;
            split2(c[a][0], c[a][1], ph, pl);
            *(uint32_t*)(smem + POFF + lrow0 * PSTR + cbase) = ph;
            *(uint32_t*)(smem + POFF + PELE + lrow0 * PSTR + cbase) = pl;
            split2(c[a][2], c[a][3], ph, pl);
            *(uint32_t*)(smem + POFF + (lrow0 + 8) * PSTR + cbase) = ph;
            *(uint32_t*)(smem + POFF + PELE + (lrow0 + 8) * PSTR + cbase) = pl;
        }
        __syncthreads();
        l0 = l0 * alpha0 + red[1][0][lrow0] + red[1][1][lrow0];
        l1 = l1 * alpha1 + red[1][0][lrow0 + 8] + red[1][1][lrow0 + 8];
        m0 = mn0; m1 = mn1;

#pragma unroll
        for (int ks = 0; ks < 4; ks++) {
            const int k0 = ks * 16;
            uint32_t pH[4], pL[4];
            ldsm4(sb + (POFF + aRow * PSTR + k0 + aCol8) * 2, pH);
            ldsm4(sb + (POFF + PELE + aRow * PSTR + k0 + aCol8) * 2, pL);
#pragma unroll
            for (int pair = 0; pair < 8; pair++) {
                const int n0 = wc * 128 + pair * 16;
                uint32_t vH[4], vL[4];
                ldsm4t(sb + (kh + (k0 + bRowPV) * QSTR + n0 + bColPV8) * 2, vH);
                ldsm4t(sb + (kl + (k0 + bRowPV) * QSTR + n0 + bColPV8) * 2, vL);
#pragma unroll
                for (int s2 = 0; s2 < 2; s2++) {
                    float* oo = Ot[pair * 2 + s2];
                    mma_bf16(oo, pH, vH + s2 * 2);
                    mma_bf16(oo, pH, vL + s2 * 2);
                    mma_bf16(oo, pL, vH + s2 * 2);
                }
            }
        }
        asm volatile("cp.async.wait_group 0;");
        __syncthreads();
    }

    // epilogue: divide by l, write [s][h*256+d]
    const float inv0 = 1.0f / l0, inv1 = 1.0f / l1;
#pragma unroll
    for (int a = 0; a < 16; a++) {
        int col = h * HD + wc * 128 + a * 8 + 2 * tc;
        *(float2*)&qo[(size_t)grow0 * (NH * HD) + col] =
            make_float2(Ot[a][0] * inv0, Ot[a][1] * inv0);
        *(float2*)&qo[(size_t)grow1 * (NH * HD) + col] =
            make_float2(Ot[a][2] * inv1, Ot[a][3] * inv1);
    }
}

// ---------------- inverse rope on O pe part (in-place) ---------------------
__global__ void o_rope_inv(float* __restrict__ o, const float* __restrict__ freqs)
{
    const int s = blockIdx.x;
    const int t = threadIdx.x;       // 512
    const int h = t >> 5, i = t & 31;
    float sn, cs;
    sincosf(freqs[s * (RR / 2) + i], &sn, &cs);
    float* p = o + s * (NH * HD) + h * HD + NOPE + 2 * i;
    float x1 = p[0], x2 = p[1];
    p[0] = fmaf(x1, cs,  x2 * sn);
    p[1] = fmaf(x2, cs, -x1 * sn);
}

// ---------------- launch ---------------------------------------------------
extern "C" void kernel_launch(void* const* d_in, const int* in_sizes, int n_in,
                              void* d_out, int out_size)
{
    const float* x         = (const float*)d_in[0];
    const float* freqs     = (const float*)d_in[1];
    const float* wq_a      = (const float*)d_in[2];
    const float* q_norm_w  = (const float*)d_in[3];
    const float* wq_b      = (const float*)d_in[4];
    const float* wkv       = (const float*)d_in[5];
    const float* kv_norm_w = (const float*)d_in[6];
    const float* wo_a_w    = (const float*)d_in[7];
    const float* wo_b      = (const float*)d_in[8];
    const float* attn_sink = (const float*)d_in[9];
    float* out = (float*)d_out;

    float *qa, *q, *kvp, *orr;
    bf16 *kvh, *kvl;
    cudaGetSymbolAddress((void**)&qa,  g_qa);
    cudaGetSymbolAddress((void**)&q,   g_q);
    cudaGetSymbolAddress((void**)&kvp, g_kvp);
    cudaGetSymbolAddress((void**)&orr, g_or);
    cudaGetSymbolAddress((void**)&kvh, g_kvh);
    cudaGetSymbolAddress((void**)&kvl, g_kvl);

    cudaFuncSetAttribute(gemm_tf32, cudaFuncAttributeMaxDynamicSharedMemorySize, GEMM_SMEM);
    cudaFuncSetAttribute(flash_mma, cudaFuncAttributeMaxDynamicSharedMemorySize, FL_SMEM);

    // q_a = x @ wq_a^T   [2048,1024]
    gemm_tf32<<<dim3(QLAT / TBN, SS / TBM), 256, GEMM_SMEM>>>(       // 0
        x, wq_a, qa, SS, QLAT, HIDD, HIDD, HIDD, QLAT, 0, 0);
    rmsnorm1024<<<SS, 256>>>(qa, q_norm_w);                          // 1
    // q = rms(q_a) @ wq_b^T   [2048,4096]
    gemm_tf32<<<dim3((NH * HD) / TBN, SS / TBM), 256, GEMM_SMEM>>>(  // 2
        qa, wq_b, q, SS, NH * HD, QLAT, QLAT, QLAT, NH * HD, 0, 0);
    // kv partials = x @ wkv^T, split-K=4 -> [4][2048,256]
    gemm_tf32<<<dim3(HD / TBN, SS / TBM, KVSPLIT), 256, GEMM_SMEM>>>( // 3 <- profiled
        x, wkv, kvp, SS, HD, HIDD, HIDD, HIDD, HD, 0, 0);
    kv_norm_rope<<<SS, 64>>>(kvp, kv_norm_w, freqs, kvh, kvl);       // 4
    // flash attention (fused q-prep) in-place on g_q
    flash_mma<<<dim3(SS / 64, NH), 256, FL_SMEM>>>(q, kvh, kvl, freqs, attn_sink); // 5
    o_rope_inv<<<SS, 512>>>(q, freqs);                               // 6
    // o_r = blockdiag(o @ wo_a^T)  [2048,2048]
    gemm_tf32<<<dim3((NG * ORNK) / TBN, SS / TBM), 256, GEMM_SMEM>>>( // 7
        q, wo_a_w, orr, SS, NG * ORNK, NG * HD, NH * HD, NG * HD, NG * ORNK, ORNK, NG * HD);
    // out = o_r @ wo_b^T [2048,2048]
    gemm_tf32<<<dim3(HIDD / TBN, SS / TBM), 256, GEMM_SMEM>>>(       // 8
        orr, wo_b, out, SS, HIDD, NG * ORNK, NG * ORNK, NG * ORNK, HIDD, 0, 0);
}

// round 15
// speedup vs baseline: 1.1979x; 1.0120x over previous
#include <cuda_runtime.h>
#include <cuda_bf16.h>
#include <math.h>
#include <stdint.h>

#define SS   2048
#define HIDD 2048
#define NH   16
#define HD   256
#define RR   64
#define NOPE 192
#define QLAT 1024
#define ORNK 512
#define NG   4
#define EPSV 1e-6f
#define SCL  0.0625f
#define KVSPLIT 4

typedef __nv_bfloat16 bf16;
typedef __nv_bfloat162 bf162;

// ---------------- scratch (static device globals; no allocations) ----------
__device__ float g_qa[SS * QLAT];
__device__ float g_q [SS * NH * HD];       // q up-proj; flash reads Q / writes O here
__device__ float g_kvp[KVSPLIT * SS * HD]; // kv split-K partials
__device__ float g_or[SS * NG * ORNK];
__device__ bf16 g_kvh[SS * HD], g_kvl[SS * HD];

// integer RNA-to-tf32: bit-identical to cvt.rna.tf32.f32 (no NaN inputs here)
__device__ __forceinline__ uint32_t rna_bits(uint32_t u) {
    return (u + 0x1000u) & 0xFFFFE000u;
}
__device__ __forceinline__ void split2(float x, float y, uint32_t& h, uint32_t& l) {
    bf162 hp, lp;
    hp.x = __float2bfloat16_rn(x);
    hp.y = __float2bfloat16_rn(y);
    lp.x = __float2bfloat16_rn(x - __bfloat162float(hp.x));
    lp.y = __float2bfloat16_rn(y - __bfloat162float(hp.y));
    h = *(uint32_t*)&hp;
    l = *(uint32_t*)&lp;
}
__device__ __forceinline__ uint32_t smem_u32(const void* p) {
    return (uint32_t)__cvta_generic_to_shared(p);
}
__device__ __forceinline__ void ldsm4(uint32_t addr, uint32_t* r) {
    asm volatile("ldmatrix.sync.aligned.m8n8.x4.shared.b16 {%0,%1,%2,%3}, [%4];"
                 : "=r"(r[0]), "=r"(r[1]), "=r"(r[2]), "=r"(r[3]) : "r"(addr));
}
__device__ __forceinline__ void ldsm4t(uint32_t addr, uint32_t* r) {
    asm volatile("ldmatrix.sync.aligned.m8n8.x4.trans.shared.b16 {%0,%1,%2,%3}, [%4];"
                 : "=r"(r[0]), "=r"(r[1]), "=r"(r[2]), "=r"(r[3]) : "r"(addr));
}
__device__ __forceinline__ void mma_bf16(float* d, const uint32_t* a, const uint32_t* b) {
    asm volatile(
        "mma.sync.aligned.m16n8k16.row.col.f32.bf16.bf16.f32 "
        "{%0,%1,%2,%3}, {%4,%5,%6,%7}, {%8,%9}, {%0,%1,%2,%3};"
        : "+f"(d[0]), "+f"(d[1]), "+f"(d[2]), "+f"(d[3])
        : "r"(a[0]), "r"(a[1]), "r"(a[2]), "r"(a[3]), "r"(b[0]), "r"(b[1]));
}

// ---------------- tf32 tensor-core NT GEMM: C = A[M,K] * B[N,K]^T ----------
// 3-stage cp.async pipeline, 2 CTAs/SM for latency hiding.
#define TBM 128
#define TBN 128
#define TBK 32
#define ASTR 36
#define STG_F ((TBM + TBN) * ASTR)
#define NSTAGE 3
#define GEMM_SMEM (NSTAGE * STG_F * 4)   // 110592 bytes

__global__ __launch_bounds__(256, 2) void gemm_tf32(
    const float* __restrict__ A, const float* __restrict__ B, float* __restrict__ C,
    int M, int N, int K, int lda, int ldb, int ldc,
    int group_n, int group_stride)
{
    extern __shared__ float sm[];
    const int bm0 = blockIdx.y * TBM;
    const int bn0 = blockIdx.x * TBN;
    const int Ksub = K / gridDim.z;
    const int kbase = blockIdx.z * Ksub;
    C += (size_t)blockIdx.z * M * ldc;
    const float* Ap = A + (group_n ? (bn0 / group_n) * (size_t)group_stride : 0);
    const int t = threadIdx.x;
    const int warp = t >> 5, lane = t & 31;
    const int wm = (warp >> 2) * 64, wn = (warp & 3) * 32;
    const int g = lane >> 2, tc = lane & 3;
    const int lrow = t >> 3, lc4 = (t & 7) * 4;

    float acc[4][4][4];
#pragma unroll
    for (int i = 0; i < 4; i++)
#pragma unroll
        for (int j = 0; j < 4; j++)
#pragma unroll
            for (int k = 0; k < 4; k++) acc[i][j][k] = 0.0f;

    const float* Agb = Ap + (size_t)(bm0 + lrow) * lda + kbase + lc4;
    const float* Bgb = B + (size_t)(bn0 + lrow) * ldb + kbase + lc4;

    auto issue = [&](int stage, int k0) {
        float* As = sm + stage * STG_F;
        float* Bs = As + TBM * ASTR;
        uint32_t sa = smem_u32(As + lrow * ASTR + lc4);
        uint32_t sb = smem_u32(Bs + lrow * ASTR + lc4);
        const float* ag = Agb + k0;
        const float* bg = Bgb + k0;
#pragma unroll
        for (int i = 0; i < 4; i++) {
            asm volatile("cp.async.cg.shared.global [%0], [%1], 16;"
                         :: "r"(sa + i * 32 * ASTR * 4), "l"(ag + (size_t)i * 32 * lda));
            asm volatile("cp.async.cg.shared.global [%0], [%1], 16;"
                         :: "r"(sb + i * 32 * ASTR * 4), "l"(bg + (size_t)i * 32 * ldb));
        }
        asm volatile("cp.async.commit_group;");
    };

    auto compute = [&](int stage) {
        const float* As = sm + stage * STG_F;
        const float* Bs = As + TBM * ASTR;
#pragma unroll
        for (int ks = 0; ks < 4; ks++) {
            uint32_t a[4][4], b[4][2];
#pragma unroll
            for (int am = 0; am < 4; am++) {
                const float* ap = As + (wm + am * 16 + g) * ASTR + ks * 8 + tc;
                a[am][0] = rna_bits(__float_as_uint(ap[0]));
                a[am][1] = rna_bits(__float_as_uint(ap[8 * ASTR]));
                a[am][2] = rna_bits(__float_as_uint(ap[4]));
                a[am][3] = rna_bits(__float_as_uint(ap[8 * ASTR + 4]));
            }
#pragma unroll
            for (int bn = 0; bn < 4; bn++) {
                const float* bp = Bs + (wn + bn * 8 + g) * ASTR + ks * 8 + tc;
                b[bn][0] = rna_bits(__float_as_uint(bp[0]));
                b[bn][1] = rna_bits(__float_as_uint(bp[4]));
            }
#pragma unroll
            for (int am = 0; am < 4; am++)
#pragma unroll
                for (int bn = 0; bn < 4; bn++)
                    asm volatile(
                        "mma.sync.aligned.m16n8k8.row.col.f32.tf32.tf32.f32 "
                        "{%0,%1,%2,%3}, {%4,%5,%6,%7}, {%8,%9}, {%0,%1,%2,%3};"
                        : "+f"(acc[am][bn][0]), "+f"(acc[am][bn][1]),
                          "+f"(acc[am][bn][2]), "+f"(acc[am][bn][3])
                        : "r"(a[am][0]), "r"(a[am][1]), "r"(a[am][2]), "r"(a[am][3]),
                          "r"(b[bn][0]), "r"(b[bn][1]));
        }
    };

    const int nk = Ksub / TBK;
    issue(0, 0);
    issue(1, TBK);

    for (int kt = 0; kt < nk; kt++) {
        asm volatile("cp.async.wait_group 1;");
        __syncthreads();
        compute(kt % 3);
        if (kt + 2 < nk) issue((kt + 2) % 3, (kt + 2) * TBK);
        else asm volatile("cp.async.commit_group;");
    }

#pragma unroll
    for (int am = 0; am < 4; am++)
#pragma unroll
        for (int bn = 0; bn < 4; bn++) {
            int row0 = bm0 + wm + am * 16 + g;
            int col = bn0 + wn + bn * 8 + tc * 2;
            *(float2*)&C[(size_t)row0 * ldc + col] =
                make_float2(acc[am][bn][0], acc[am][bn][1]);
            *(float2*)&C[(size_t)(row0 + 8) * ldc + col] =
                make_float2(acc[am][bn][2], acc[am][bn][3]);
        }
}

// ---------------- rmsnorm over 1024 cols (in-place) ------------------------
__global__ void rmsnorm1024(float* __restrict__ x, const float* __restrict__ w)
{
    const int row = blockIdx.x;
    float* xr = x + row * QLAT;
    const int t = threadIdx.x; // 256
    float4 v = ((float4*)xr)[t];
    float ssq = v.x * v.x + v.y * v.y + v.z * v.z + v.w * v.w;
#pragma unroll
    for (int o = 16; o > 0; o >>= 1) ssq += __shfl_xor_sync(0xffffffffu, ssq, o);
    __shared__ float ws[8];
    if ((t & 31) == 0) ws[t >> 5] = ssq;
    __syncthreads();
    float tot = ws[0] + ws[1] + ws[2] + ws[3] + ws[4] + ws[5] + ws[6] + ws[7];
    float sc = rsqrtf(tot / (float)QLAT + EPSV);
    float4 wv = ((const float4*)w)[t];
    v.x *= sc * wv.x; v.y *= sc * wv.y; v.z *= sc * wv.z; v.w *= sc * wv.w;
    ((float4*)xr)[t] = v;
}

// --- kv: sum split-K partials + rmsnorm(256) + rope -> bf16 hi/lo ----------
__global__ void kv_norm_rope(const float* __restrict__ kvp, const float* __restrict__ w,
                             const float* __restrict__ freqs,
                             bf16* __restrict__ kvh, bf16* __restrict__ kvl)
{
    const int s = blockIdx.x;
    const int t = threadIdx.x; // 64
    float4 v = ((const float4*)(kvp + (size_t)s * HD))[t];
#pragma unroll
    for (int z = 1; z < KVSPLIT; z++) {
        float4 p = ((const float4*)(kvp + (size_t)z * SS * HD + (size_t)s * HD))[t];
        v.x += p.x; v.y += p.y; v.z += p.z; v.w += p.w;
    }
    float ssq = v.x * v.x + v.y * v.y + v.z * v.z + v.w * v.w;
#pragma unroll
    for (int o = 16; o > 0; o >>= 1) ssq += __shfl_xor_sync(0xffffffffu, ssq, o);
    __shared__ float ws[2];
    if ((t & 31) == 0) ws[t >> 5] = ssq;
    __syncthreads();
    float sc = rsqrtf((ws[0] + ws[1]) / (float)HD + EPSV);
    float4 wv = ((const float4*)w)[t];
    v.x *= sc * wv.x; v.y *= sc * wv.y; v.z *= sc * wv.z; v.w *= sc * wv.w;
    const int c = t * 4;
    if (c >= NOPE) {
        int i0 = (c - NOPE) >> 1;
        float sn0, cs0, sn1, cs1;
        sincosf(freqs[s * (RR / 2) + i0], &sn0, &cs0);
        sincosf(freqs[s * (RR / 2) + i0 + 1], &sn1, &cs1);
        float x1 = v.x, x2 = v.y;
        v.x = x1 * cs0 - x2 * sn0; v.y = x1 * sn0 + x2 * cs0;
        x1 = v.z; x2 = v.w;
        v.z = x1 * cs1 - x2 * sn1; v.w = x1 * sn1 + x2 * cs1;
    }
    uint32_t h0, l0, h1, l1;
    split2(v.x, v.y, h0, l0);
    split2(v.z, v.w, h1, l1);
    *(uint2*)&kvh[s * HD + c] = make_uint2(h0, h1);
    *(uint2*)&kvl[s * HD + c] = make_uint2(l0, l1);
}

// ============ flash attention via bf16-split mma.sync (K == V) =============
// qb reversed (longest CTAs first) + fused q-prep + fused inverse rope.
#define QSTR 264
#define PSTR 72
#define QELE (64 * QSTR)
#define KOFF (2 * QELE)
#define KPAIR (2 * QELE)
#define POFF (KOFF + 2 * KPAIR)
#define PELE (64 * PSTR)
#define FL_SMEM ((POFF + 2 * PELE) * 2)

__global__ __launch_bounds__(256, 1) void flash_mma(
    float* __restrict__ qo,
    const bf16* __restrict__ kvh, const bf16* __restrict__ kvl,
    const float* __restrict__ freqs,
    const float* __restrict__ sink)
{
    extern __shared__ __align__(16) bf16 smem[];
    __shared__ float red[2][2][64];

    const int qb = (int)gridDim.x - 1 - (int)blockIdx.x;  // longest-first
    const int h  = blockIdx.y;
    const int t  = threadIdx.x;
    const int warp = t >> 5, lane = t & 31;
    const int wr = warp >> 1, wc = warp & 1;
    const int g = lane >> 2, tc = lane & 3;

    const uint32_t sb = smem_u32(smem);
    const int aRow = wr * 16 + (lane & 7) + ((lane >> 3) & 1) * 8;
    const int aCol8 = (lane >> 4) * 8;
    const int bRowQK = (lane & 7) + ((lane >> 4) & 1) * 8;
    const int bColQK8 = ((lane >> 3) & 1) * 8;
    const int bRowPV = (lane & 7) + ((lane >> 3) & 1) * 8;
    const int bColPV8 = ((lane >> 4) & 1) * 8;

    auto issue_kv = [&](int stage, int kb) {
        const size_t kbase = (size_t)(kb * 64) * HD;
        uint32_t koff = KOFF + stage * KPAIR;
        for (int i = t; i < 2048; i += 256) {
            int r = i >> 5, cb = i & 31;
            uint32_t dh = sb + (koff + r * QSTR + cb * 8) * 2;
            uint32_t dl = sb + (koff + QELE + r * QSTR + cb * 8) * 2;
            const bf16* srh = kvh + kbase + r * HD + cb * 8;
            const bf16* srl = kvl + kbase + r * HD + cb * 8;
            asm volatile("cp.async.cg.shared.global [%0], [%1], 16;" :: "r"(dh), "l"(srh));
            asm volatile("cp.async.cg.shared.global [%0], [%1], 16;" :: "r"(dl), "l"(srl));
        }
        asm volatile("cp.async.commit_group;");
    };
    issue_kv(0, 0);

    // fused Q prep: per-head rms + rope + hi/lo split -> smem
    {
        const int r = t >> 2, quad = t & 3;
        const int srow = qb * 64 + r;
        const float* qrow = qo + (size_t)srow * (NH * HD) + h * HD + quad * 64;
        float ssq = 0.0f;
#pragma unroll
        for (int j = 0; j < 16; j++) {
            float4 v = ((const float4*)qrow)[j];
            ssq += v.x * v.x + v.y * v.y + v.z * v.z + v.w * v.w;
        }
        ssq += __shfl_xor_sync(0xffffffffu, ssq, 1);
        ssq += __shfl_xor_sync(0xffffffffu, ssq, 2);
        const float sc = rsqrtf(ssq / (float)HD + EPSV);
        const bool pe = (quad == 3);
#pragma unroll
        for (int j = 0; j < 16; j++) {
            float4 v = ((const float4*)qrow)[j];
            v.x *= sc; v.y *= sc; v.z *= sc; v.w *= sc;
            if (pe) {
                float sn, cs, x1, x2;
                sincosf(freqs[srow * (RR / 2) + 2 * j], &sn, &cs);
                x1 = v.x; x2 = v.y; v.x = x1 * cs - x2 * sn; v.y = x1 * sn + x2 * cs;
                sincosf(freqs[srow * (RR / 2) + 2 * j + 1], &sn, &cs);
                x1 = v.z; x2 = v.w; v.z = x1 * cs - x2 * sn; v.w = x1 * sn + x2 * cs;
            }
            uint32_t h0, l0, h1, l1;
            split2(v.x, v.y, h0, l0);
            split2(v.z, v.w, h1, l1);
            const int d = quad * 64 + j * 4;
            *(uint2*)(smem + r * QSTR + d) = make_uint2(h0, h1);
            *(uint2*)(smem + QELE + r * QSTR + d) = make_uint2(l0, l1);
        }
    }
    asm volatile("cp.async.wait_group 0;");
    __syncthreads();

    float Ot[16][4];
#pragma unroll
    for (int a = 0; a < 16; a++)
#pragma unroll
        for (int e = 0; e < 4; e++) Ot[a][e] = 0.0f;
    const float snk = sink[h];
    float m0 = snk, m1 = snk, l0 = 1.0f, l1 = 1.0f;

    const int grow0 = qb * 64 + wr * 16 + g;
    const int grow1 = grow0 + 8;
    const int lrow0 = wr * 16 + g;

    for (int kb = 0; kb <= qb; kb++) {
        const int cur = kb & 1;
        const uint32_t kh = KOFF + cur * KPAIR;
        const uint32_t kl = kh + QELE;

        float c[4][4];
#pragma unroll
        for (int a = 0; a < 4; a++)
#pragma unroll
            for (int e = 0; e < 4; e++) c[a][e] = 0.0f;

#pragma unroll 4
        for (int ks = 0; ks < 16; ks++) {
            const int k0 = ks * 16;
            uint32_t aH[4], aL[4];
            ldsm4(sb + (aRow * QSTR + k0 + aCol8) * 2, aH);
            ldsm4(sb + (QELE + aRow * QSTR + k0 + aCol8) * 2, aL);
#pragma unroll
            for (int pair = 0; pair < 2; pair++) {
                const int j0 = wc * 32 + pair * 16;
                uint32_t bH[4], bL[4];
                ldsm4(sb + (kh + (j0 + bRowQK) * QSTR + k0 + bColQK8) * 2, bH);
                ldsm4(sb + (kl + (j0 + bRowQK) * QSTR + k0 + bColQK8) * 2, bL);
#pragma unroll
                for (int s2 = 0; s2 < 2; s2++) {
                    float* cc = c[pair * 2 + s2];
                    mma_bf16(cc, aH, bH + s2 * 2);
                    mma_bf16(cc, aH, bL + s2 * 2);
                    mma_bf16(cc, aL, bH + s2 * 2);
                }
            }
        }

        if (kb < qb) issue_kv(cur ^ 1, kb + 1);
        else asm volatile("cp.async.commit_group;");

        const bool diag = (kb == qb);
#pragma unroll
        for (int a = 0; a < 4; a++) {
            int colb = kb * 64 + wc * 32 + a * 8 + 2 * tc;
            c[a][0] *= SCL; c[a][1] *= SCL; c[a][2] *= SCL; c[a][3] *= SCL;
            if (diag) {
                if (colb     > grow0) c[a][0] = -3.0e38f;
                if (colb + 1 > grow0) c[a][1] = -3.0e38f;
                if (colb     > grow1) c[a][2] = -3.0e38f;
                if (colb + 1 > grow1) c[a][3] = -3.0e38f;
            }
        }

        float tmax0 = -3.0e38f, tmax1 = -3.0e38f;
#pragma unroll
        for (int a = 0; a < 4; a++) {
            tmax0 = fmaxf(tmax0, fmaxf(c[a][0], c[a][1]));
            tmax1 = fmaxf(tmax1, fmaxf(c[a][2], c[a][3]));
        }
        tmax0 = fmaxf(tmax0, __shfl_xor_sync(0xffffffffu, tmax0, 1));
        tmax0 = fmaxf(tmax0, __shfl_xor_sync(0xffffffffu, tmax0, 2));
        tmax1 = fmaxf(tmax1, __shfl_xor_sync(0xffffffffu, tmax1, 1));
        tmax1 = fmaxf(tmax1, __shfl_xor_sync(0xffffffffu, tmax1, 2));
        if (tc == 0) {
            red[0][wc][lrow0] = tmax0;
            red[0][wc][lrow0 + 8] = tmax1;
        }
        __syncthreads();
        float mn0 = fmaxf(m0, fmaxf(red[0][0][lrow0], red[0][1][lrow0]));
        float mn1 = fmaxf(m1, fmaxf(red[0][0][lrow0 + 8], red[0][1][lrow0 + 8]));
        float alpha0 = __expf(m0 - mn0);
        float alpha1 = __expf(m1 - mn1);
#pragma unroll
        for (int a = 0; a < 16; a++) {
            Ot[a][0] *= alpha0; Ot[a][1] *= alpha0;
            Ot[a][2] *= alpha1; Ot[a][3] *= alpha1;
        }
        float tsum0 = 0.0f, tsum1 = 0.0f;
#pragma unroll
        for (int a = 0; a < 4; a++) {
            c[a][0] = __expf(c[a][0] - mn0);
            c[a][1] = __expf(c[a][1] - mn0);
            c[a][2] = __expf(c[a][2] - mn1);
            c[a][3] = __expf(c[a][3] - mn1);
            tsum0 += c[a][0] + c[a][1];
            tsum1 += c[a][2] + c[a][3];
        }
        tsum0 += __shfl_xor_sync(0xffffffffu, tsum0, 1);
        tsum0 += __shfl_xor_sync(0xffffffffu, tsum0, 2);
        tsum1 += __shfl_xor_sync(0xffffffffu, tsum1, 1);
        tsum1 += __shfl_xor_sync(0xffffffffu, tsum1, 2);
        if (tc == 0) {
            red[1][wc][lrow0] = tsum0;
            red[1][wc][lrow0 + 8] = tsum1;
        }
#pragma unroll
        for (int a = 0; a < 4; a++) {
            int cbase = wc * 32 + a * 8 + 2 * tc;
            uint32_t ph, pl;
            split2(c[a][0], c[a][1], ph, pl);
            *(uint32_t*)(smem + POFF + lrow0 * PSTR + cbase) = ph;
            *(uint32_t*)(smem + POFF + PELE + lrow0 * PSTR + cbase) = pl;
            split2(c[a][2], c[a][3], ph, pl);
            *(uint32_t*)(smem + POFF + (lrow0 + 8) * PSTR + cbase) = ph;
            *(uint32_t*)(smem + POFF + PELE + (lrow0 + 8) * PSTR + cbase) = pl;
        }
        __syncthreads();
        l0 = l0 * alpha0 + red[1][0][lrow0] + red[1][1][lrow0];
        l1 = l1 * alpha1 + red[1][0][lrow0 + 8] + red[1][1][lrow0 + 8];
        m0 = mn0; m1 = mn1;

#pragma unroll
        for (int ks = 0; ks < 4; ks++) {
            const int k0 = ks * 16;
            uint32_t pH[4], pL[4];
            ldsm4(sb + (POFF + aRow * PSTR + k0 + aCol8) * 2, pH);
            ldsm4(sb + (POFF + PELE + aRow * PSTR + k0 + aCol8) * 2, pL);
#pragma unroll
            for (int pair = 0; pair < 8; pair++) {
                const int n0 = wc * 128 + pair * 16;
                uint32_t vH[4], vL[4];
                ldsm4t(sb + (kh + (k0 + bRowPV) * QSTR + n0 + bColPV8) * 2, vH);
                ldsm4t(sb + (kl + (k0 + bRowPV) * QSTR + n0 + bColPV8) * 2, vL);
#pragma unroll
                for (int s2 = 0; s2 < 2; s2++) {
                    float* oo = Ot[pair * 2 + s2];
                    mma_bf16(oo, pH, vH + s2 * 2);
                    mma_bf16(oo, pH, vL + s2 * 2);
                    mma_bf16(oo, pL, vH + s2 * 2);
                }
            }
        }
        asm volatile("cp.async.wait_group 0;");
        __syncthreads();
    }

    // epilogue: divide by l, fused inverse rope on pe pairs, write [s][h*256+d]
    const float inv0 = 1.0f / l0, inv1 = 1.0f / l1;
#pragma unroll
    for (int a = 0; a < 16; a++) {
        const int d = wc * 128 + a * 8 + 2 * tc;
        float v00 = Ot[a][0] * inv0, v01 = Ot[a][1] * inv0;
        float v10 = Ot[a][2] * inv1, v11 = Ot[a][3] * inv1;
        if (wc == 1 && a >= 8) {            // pe region: d >= 192, (d, d+1) pair
            const int i = (d - NOPE) >> 1;
            float sn, cs, x1, x2;
            sincosf(freqs[grow0 * (RR / 2) + i], &sn, &cs);
            x1 = v00; x2 = v01;
            v00 = fmaf(x1, cs,  x2 * sn);
            v01 = fmaf(x2, cs, -x1 * sn);
            sincosf(freqs[grow1 * (RR / 2) + i], &sn, &cs);
            x1 = v10; x2 = v11;
            v10 = fmaf(x1, cs,  x2 * sn);
            v11 = fmaf(x2, cs, -x1 * sn);
        }
        const int col = h * HD + d;
        *(float2*)&qo[(size_t)grow0 * (NH * HD) + col] = make_float2(v00, v01);
        *(float2*)&qo[(size_t)grow1 * (NH * HD) + col] = make_float2(v10, v11);
    }
}

// ---------------- launch ---------------------------------------------------
extern "C" void kernel_launch(void* const* d_in, const int* in_sizes, int n_in,
                              void* d_out, int out_size)
{
    const float* x         = (const float*)d_in[0];
    const float* freqs     = (const float*)d_in[1];
    const float* wq_a      = (const float*)d_in[2];
    const float* q_norm_w  = (const float*)d_in[3];
    const float* wq_b      = (const float*)d_in[4];
    const float* wkv       = (const float*)d_in[5];
    const float* kv_norm_w = (const float*)d_in[6];
    const float* wo_a_w    = (const float*)d_in[7];
    const float* wo_b      = (const float*)d_in[8];
    const float* attn_sink = (const float*)d_in[9];
    float* out = (float*)d_out;

    float *qa, *q, *kvp, *orr;
    bf16 *kvh, *kvl;
    cudaGetSymbolAddress((void**)&qa,  g_qa);
    cudaGetSymbolAddress((void**)&q,   g_q);
    cudaGetSymbolAddress((void**)&kvp, g_kvp);
    cudaGetSymbolAddress((void**)&orr, g_or);
    cudaGetSymbolAddress((void**)&kvh, g_kvh);
    cudaGetSymbolAddress((void**)&kvl, g_kvl);

    cudaFuncSetAttribute(gemm_tf32, cudaFuncAttributeMaxDynamicSharedMemorySize, GEMM_SMEM);
    cudaFuncSetAttribute(flash_mma, cudaFuncAttributeMaxDynamicSharedMemorySize, FL_SMEM);

    // q_a = x @ wq_a^T   [2048,1024]
    gemm_tf32<<<dim3(QLAT / TBN, SS / TBM), 256, GEMM_SMEM>>>(       // 0
        x, wq_a, qa, SS, QLAT, HIDD, HIDD, HIDD, QLAT, 0, 0);
    rmsnorm1024<<<SS, 256>>>(qa, q_norm_w);                          // 1
    // q = rms(q_a) @ wq_b^T   [2048,4096]
    gemm_tf32<<<dim3((NH * HD) / TBN, SS / TBM), 256, GEMM_SMEM>>>(  // 2
        qa, wq_b, q, SS, NH * HD, QLAT, QLAT, QLAT, NH * HD, 0, 0);
    // kv partials = x @ wkv^T, split-K=4 -> [4][2048,256]
    gemm_tf32<<<dim3(HD / TBN, SS / TBM, KVSPLIT), 256, GEMM_SMEM>>>( // 3 <- profiled
        x, wkv, kvp, SS, HD, HIDD, HIDD, HIDD, HD, 0, 0);
    kv_norm_rope<<<SS, 64>>>(kvp, kv_norm_w, freqs, kvh, kvl);       // 4
    // flash attention (fused q-prep + inverse rope) in-place on g_q
    flash_mma<<<dim3(SS / 64, NH), 256, FL_SMEM>>>(q, kvh, kvl, freqs, attn_sink); // 5
    // o_r = blockdiag(o @ wo_a^T)  [2048,2048]
    gemm_tf32<<<dim3((NG * ORNK) / TBN, SS / TBM), 256, GEMM_SMEM>>>( // 6
        q, wo_a_w, orr, SS, NG * ORNK, NG * HD, NH * HD, NG * HD, NG * ORNK, ORNK, NG * HD);
    // out = o_r @ wo_b^T [2048,2048]
    gemm_tf32<<<dim3(HIDD / TBN, SS / TBM), 256, GEMM_SMEM>>>(       // 7
        orr, wo_b, out, SS, HIDD, NG * ORNK, NG * ORNK, NG * ORNK, HIDD, 0, 0);
}

// round 16
// speedup vs baseline: 1.2111x; 1.0111x over previous
#include <cuda_runtime.h>
#include <cuda_bf16.h>
#include <math.h>
#include <stdint.h>

#define SS   2048
#define HIDD 2048
#define NH   16
#define HD   256
#define RR   64
#define NOPE 192
#define QLAT 1024
#define ORNK 512
#define NG   4
#define EPSV 1e-6f
#define SCL  0.0625f
#define KVSPLIT 8
#define QSPLIT 2

typedef __nv_bfloat16 bf16;
typedef __nv_bfloat162 bf162;

// ---------------- scratch (static device globals; no allocations) ----------
__device__ float g_qap[QSPLIT * SS * QLAT]; // q_a split-K partials
__device__ float g_qa [SS * QLAT];
__device__ float g_q  [SS * NH * HD];       // q up-proj; flash reads Q / writes O here
__device__ float g_kvp[KVSPLIT * SS * HD];  // kv split-K partials
__device__ float g_or [SS * NG * ORNK];
__device__ bf16 g_kvh[SS * HD], g_kvl[SS * HD];

// integer RNA-to-tf32: bit-identical to cvt.rna.tf32.f32 (no NaN inputs here)
__device__ __forceinline__ uint32_t rna_bits(uint32_t u) {
    return (u + 0x1000u) & 0xFFFFE000u;
}
__device__ __forceinline__ void split2(float x, float y, uint32_t& h, uint32_t& l) {
    bf162 hp, lp;
    hp.x = __float2bfloat16_rn(x);
    hp.y = __float2bfloat16_rn(y);
    lp.x = __float2bfloat16_rn(x - __bfloat162float(hp.x));
    lp.y = __float2bfloat16_rn(y - __bfloat162float(hp.y));
    h = *(uint32_t*)&hp;
    l = *(uint32_t*)&lp;
}
__device__ __forceinline__ uint32_t smem_u32(const void* p) {
    return (uint32_t)__cvta_generic_to_shared(p);
}
__device__ __forceinline__ void ldsm4(uint32_t addr, uint32_t* r) {
    asm volatile("ldmatrix.sync.aligned.m8n8.x4.shared.b16 {%0,%1,%2,%3}, [%4];"
                 : "=r"(r[0]), "=r"(r[1]), "=r"(r[2]), "=r"(r[3]) : "r"(addr));
}
__device__ __forceinline__ void ldsm4t(uint32_t addr, uint32_t* r) {
    asm volatile("ldmatrix.sync.aligned.m8n8.x4.trans.shared.b16 {%0,%1,%2,%3}, [%4];"
                 : "=r"(r[0]), "=r"(r[1]), "=r"(r[2]), "=r"(r[3]) : "r"(addr));
}
__device__ __forceinline__ void mma_bf16(float* d, const uint32_t* a, const uint32_t* b) {
    asm volatile(
        "mma.sync.aligned.m16n8k16.row.col.f32.bf16.bf16.f32 "
        "{%0,%1,%2,%3}, {%4,%5,%6,%7}, {%8,%9}, {%0,%1,%2,%3};"
        : "+f"(d[0]), "+f"(d[1]), "+f"(d[2]), "+f"(d[3])
        : "r"(a[0]), "r"(a[1]), "r"(a[2]), "r"(a[3]), "r"(b[0]), "r"(b[1]));
}

// ---------------- tf32 tensor-core NT GEMM: C = A[M,K] * B[N,K]^T ----------
// 3-stage cp.async pipeline, 2 CTAs/SM; split-K via blockIdx.z planes.
#define TBM 128
#define TBN 128
#define TBK 32
#define ASTR 36
#define STG_F ((TBM + TBN) * ASTR)
#define NSTAGE 3
#define GEMM_SMEM (NSTAGE * STG_F * 4)   // 110592 bytes

__global__ __launch_bounds__(256, 2) void gemm_tf32(
    const float* __restrict__ A, const float* __restrict__ B, float* __restrict__ C,
    int M, int N, int K, int lda, int ldb, int ldc,
    int group_n, int group_stride)
{
    extern __shared__ float sm[];
    const int bm0 = blockIdx.y * TBM;
    const int bn0 = blockIdx.x * TBN;
    const int Ksub = K / gridDim.z;
    const int kbase = blockIdx.z * Ksub;
    C += (size_t)blockIdx.z * M * ldc;
    const float* Ap = A + (group_n ? (bn0 / group_n) * (size_t)group_stride : 0);
    const int t = threadIdx.x;
    const int warp = t >> 5, lane = t & 31;
    const int wm = (warp >> 2) * 64, wn = (warp & 3) * 32;
    const int g = lane >> 2, tc = lane & 3;
    const int lrow = t >> 3, lc4 = (t & 7) * 4;

    float acc[4][4][4];
#pragma unroll
    for (int i = 0; i < 4; i++)
#pragma unroll
        for (int j = 0; j < 4; j++)
#pragma unroll
            for (int k = 0; k < 4; k++) acc[i][j][k] = 0.0f;

    const float* Agb = Ap + (size_t)(bm0 + lrow) * lda + kbase + lc4;
    const float* Bgb = B + (size_t)(bn0 + lrow) * ldb + kbase + lc4;

    auto issue = [&](int stage, int k0) {
        float* As = sm + stage * STG_F;
        float* Bs = As + TBM * ASTR;
        uint32_t sa = smem_u32(As + lrow * ASTR + lc4);
        uint32_t sb = smem_u32(Bs + lrow * ASTR + lc4);
        const float* ag = Agb + k0;
        const float* bg = Bgb + k0;
#pragma unroll
        for (int i = 0; i < 4; i++) {
            asm volatile("cp.async.cg.shared.global [%0], [%1], 16;"
                         :: "r"(sa + i * 32 * ASTR * 4), "l"(ag + (size_t)i * 32 * lda));
            asm volatile("cp.async.cg.shared.global [%0], [%1], 16;"
                         :: "r"(sb + i * 32 * ASTR * 4), "l"(bg + (size_t)i * 32 * ldb));
        }
        asm volatile("cp.async.commit_group;");
    };

    auto compute = [&](int stage) {
        const float* As = sm + stage * STG_F;
        const float* Bs = As + TBM * ASTR;
#pragma unroll
        for (int ks = 0; ks < 4; ks++) {
            uint32_t a[4][4], b[4][2];
#pragma unroll
            for (int am = 0; am < 4; am++) {
                const float* ap = As + (wm + am * 16 + g) * ASTR + ks * 8 + tc;
                a[am][0] = rna_bits(__float_as_uint(ap[0]));
                a[am][1] = rna_bits(__float_as_uint(ap[8 * ASTR]));
                a[am][2] = rna_bits(__float_as_uint(ap[4]));
                a[am][3] = rna_bits(__float_as_uint(ap[8 * ASTR + 4]));
            }
#pragma unroll
            for (int bn = 0; bn < 4; bn++) {
                const float* bp = Bs + (wn + bn * 8 + g) * ASTR + ks * 8 + tc;
                b[bn][0] = rna_bits(__float_as_uint(bp[0]));
                b[bn][1] = rna_bits(__float_as_uint(bp[4]));
            }
#pragma unroll
            for (int am = 0; am < 4; am++)
#pragma unroll
                for (int bn = 0; bn < 4; bn++)
                    asm volatile(
                        "mma.sync.aligned.m16n8k8.row.col.f32.tf32.tf32.f32 "
                        "{%0,%1,%2,%3}, {%4,%5,%6,%7}, {%8,%9}, {%0,%1,%2,%3};"
                        : "+f"(acc[am][bn][0]), "+f"(acc[am][bn][1]),
                          "+f"(acc[am][bn][2]), "+f"(acc[am][bn][3])
                        : "r"(a[am][0]), "r"(a[am][1]), "r"(a[am][2]), "r"(a[am][3]),
                          "r"(b[bn][0]), "r"(b[bn][1]));
        }
    };

    const int nk = Ksub / TBK;   // >= 8 for all uses
    issue(0, 0);
    issue(1, TBK);

    for (int kt = 0; kt < nk; kt++) {
        asm volatile("cp.async.wait_group 1;");
        __syncthreads();
        compute(kt % 3);
        if (kt + 2 < nk) issue((kt + 2) % 3, (kt + 2) * TBK);
        else asm volatile("cp.async.commit_group;");
    }

#pragma unroll
    for (int am = 0; am < 4; am++)
#pragma unroll
        for (int bn = 0; bn < 4; bn++) {
            int row0 = bm0 + wm + am * 16 + g;
            int col = bn0 + wn + bn * 8 + tc * 2;
            *(float2*)&C[(size_t)row0 * ldc + col] =
                make_float2(acc[am][bn][0], acc[am][bn][1]);
            *(float2*)&C[(size_t)(row0 + 8) * ldc + col] =
                make_float2(acc[am][bn][2], acc[am][bn][3]);
        }
}

// ------- rmsnorm over 1024 cols: sum QSPLIT partials, norm, write ----------
__global__ void rmsnorm1024(const float* __restrict__ xp, const float* __restrict__ w,
                            float* __restrict__ out)
{
    const int row = blockIdx.x;
    const int t = threadIdx.x; // 256
    float4 v = ((const float4*)(xp + (size_t)row * QLAT))[t];
#pragma unroll
    for (int z = 1; z < QSPLIT; z++) {
        float4 p = ((const float4*)(xp + (size_t)z * SS * QLAT + (size_t)row * QLAT))[t];
        v.x += p.x; v.y += p.y; v.z += p.z; v.w += p.w;
    }
    float ssq = v.x * v.x + v.y * v.y + v.z * v.z + v.w * v.w;
#pragma unroll
    for (int o = 16; o > 0; o >>= 1) ssq += __shfl_xor_sync(0xffffffffu, ssq, o);
    __shared__ float ws[8];
    if ((t & 31) == 0) ws[t >> 5] = ssq;
    __syncthreads();
    float tot = ws[0] + ws[1] + ws[2] + ws[3] + ws[4] + ws[5] + ws[6] + ws[7];
    float sc = rsqrtf(tot / (float)QLAT + EPSV);
    float4 wv = ((const float4*)w)[t];
    v.x *= sc * wv.x; v.y *= sc * wv.y; v.z *= sc * wv.z; v.w *= sc * wv.w;
    ((float4*)(out + (size_t)row * QLAT))[t] = v;
}

// --- kv: sum split-K partials + rmsnorm(256) + rope -> bf16 hi/lo ----------
__global__ void kv_norm_rope(const float* __restrict__ kvp, const float* __restrict__ w,
                             const float* __restrict__ freqs,
                             bf16* __restrict__ kvh, bf16* __restrict__ kvl)
{
    const int s = blockIdx.x;
    const int t = threadIdx.x; // 64
    float4 v = ((const float4*)(kvp + (size_t)s * HD))[t];
#pragma unroll
    for (int z = 1; z < KVSPLIT; z++) {
        float4 p = ((const float4*)(kvp + (size_t)z * SS * HD + (size_t)s * HD))[t];
        v.x += p.x; v.y += p.y; v.z += p.z; v.w += p.w;
    }
    float ssq = v.x * v.x + v.y * v.y + v.z * v.z + v.w * v.w;
#pragma unroll
    for (int o = 16; o > 0; o >>= 1) ssq += __shfl_xor_sync(0xffffffffu, ssq, o);
    __shared__ float ws[2];
    if ((t & 31) == 0) ws[t >> 5] = ssq;
    __syncthreads();
    float sc = rsqrtf((ws[0] + ws[1]) / (float)HD + EPSV);
    float4 wv = ((const float4*)w)[t];
    v.x *= sc * wv.x; v.y *= sc * wv.y; v.z *= sc * wv.z; v.w *= sc * wv.w;
    const int c = t * 4;
    if (c >= NOPE) {
        int i0 = (c - NOPE) >> 1;
        float sn0, cs0, sn1, cs1;
        sincosf(freqs[s * (RR / 2) + i0], &sn0, &cs0);
        sincosf(freqs[s * (RR / 2) + i0 + 1], &sn1, &cs1);
        float x1 = v.x, x2 = v.y;
        v.x = x1 * cs0 - x2 * sn0; v.y = x1 * sn0 + x2 * cs0;
        x1 = v.z; x2 = v.w;
        v.z = x1 * cs1 - x2 * sn1; v.w = x1 * sn1 + x2 * cs1;
    }
    uint32_t h0, l0, h1, l1;
    split2(v.x, v.y, h0, l0);
    split2(v.z, v.w, h1, l1);
    *(uint2*)&kvh[s * HD + c] = make_uint2(h0, h1);
    *(uint2*)&kvl[s * HD + c] = make_uint2(l0, l1);
}

// ============ flash attention via bf16-split mma.sync (K == V) =============
#define QSTR 264
#define PSTR 72
#define QELE (64 * QSTR)
#define KOFF (2 * QELE)
#define KPAIR (2 * QELE)
#define POFF (KOFF + 2 * KPAIR)
#define PELE (64 * PSTR)
#define FL_SMEM ((POFF + 2 * PELE) * 2)

__global__ __launch_bounds__(256, 1) void flash_mma(
    float* __restrict__ qo,
    const bf16* __restrict__ kvh, const bf16* __restrict__ kvl,
    const float* __restrict__ freqs,
    const float* __restrict__ sink)
{
    extern __shared__ __align__(16) bf16 smem[];
    __shared__ float red[2][2][64];

    const int qb = (int)gridDim.x - 1 - (int)blockIdx.x;  // longest-first
    const int h  = blockIdx.y;
    const int t  = threadIdx.x;
    const int warp = t >> 5, lane = t & 31;
    const int wr = warp >> 1, wc = warp & 1;
    const int g = lane >> 2, tc = lane & 3;

    const uint32_t sb = smem_u32(smem);
    const int aRow = wr * 16 + (lane & 7) + ((lane >> 3) & 1) * 8;
    const int aCol8 = (lane >> 4) * 8;
    const int bRowQK = (lane & 7) + ((lane >> 4) & 1) * 8;
    const int bColQK8 = ((lane >> 3) & 1) * 8;
    const int bRowPV = (lane & 7) + ((lane >> 3) & 1) * 8;
    const int bColPV8 = ((lane >> 4) & 1) * 8;

    auto issue_kv = [&](int stage, int kb) {
        const size_t kbase = (size_t)(kb * 64) * HD;
        uint32_t koff = KOFF + stage * KPAIR;
        for (int i = t; i < 2048; i += 256) {
            int r = i >> 5, cb = i & 31;
            uint32_t dh = sb + (koff + r * QSTR + cb * 8) * 2;
            uint32_t dl = sb + (koff + QELE + r * QSTR + cb * 8) * 2;
            const bf16* srh = kvh + kbase + r * HD + cb * 8;
            const bf16* srl = kvl + kbase + r * HD + cb * 8;
            asm volatile("cp.async.cg.shared.global [%0], [%1], 16;" :: "r"(dh), "l"(srh));
            asm volatile("cp.async.cg.shared.global [%0], [%1], 16;" :: "r"(dl), "l"(srl));
        }
        asm volatile("cp.async.commit_group;");
    };
    issue_kv(0, 0);

    // fused Q prep: per-head rms + rope + hi/lo split -> smem
    {
        const int r = t >> 2, quad = t & 3;
        const int srow = qb * 64 + r;
        const float* qrow = qo + (size_t)srow * (NH * HD) + h * HD + quad * 64;
        float ssq = 0.0f;
#pragma unroll
        for (int j = 0; j < 16; j++) {
            float4 v = ((const float4*)qrow)[j];
            ssq += v.x * v.x + v.y * v.y + v.z * v.z + v.w * v.w;
        }
        ssq += __shfl_xor_sync(0xffffffffu, ssq, 1);
        ssq += __shfl_xor_sync(0xffffffffu, ssq, 2);
        const float sc = rsqrtf(ssq / (float)HD + EPSV);
        const bool pe = (quad == 3);
#pragma unroll
        for (int j = 0; j < 16; j++) {
            float4 v = ((const float4*)qrow)[j];
            v.x *= sc; v.y *= sc; v.z *= sc; v.w *= sc;
            if (pe) {
                float sn, cs, x1, x2;
                sincosf(freqs[srow * (RR / 2) + 2 * j], &sn, &cs);
                x1 = v.x; x2 = v.y; v.x = x1 * cs - x2 * sn; v.y = x1 * sn + x2 * cs;
                sincosf(freqs[srow * (RR / 2) + 2 * j + 1], &sn, &cs);
                x1 = v.z; x2 = v.w; v.z = x1 * cs - x2 * sn; v.w = x1 * sn + x2 * cs;
            }
            uint32_t h0, l0, h1, l1;
            split2(v.x, v.y, h0, l0);
            split2(v.z, v.w, h1, l1);
            const int d = quad * 64 + j * 4;
            *(uint2*)(smem + r * QSTR + d) = make_uint2(h0, h1);
            *(uint2*)(smem + QELE + r * QSTR + d) = make_uint2(l0, l1);
        }
    }
    asm volatile("cp.async.wait_group 0;");
    __syncthreads();

    float Ot[16][4];
#pragma unroll
    for (int a = 0; a < 16; a++)
#pragma unroll
        for (int e = 0; e < 4; e++) Ot[a][e] = 0.0f;
    const float snk = sink[h];
    float m0 = snk, m1 = snk, l0 = 1.0f, l1 = 1.0f;

    const int grow0 = qb * 64 + wr * 16 + g;
    const int grow1 = grow0 + 8;
    const int lrow0 = wr * 16 + g;

    for (int kb = 0; kb <= qb; kb++) {
        const int cur = kb & 1;
        const uint32_t kh = KOFF + cur * KPAIR;
        const uint32_t kl = kh + QELE;

        float c[4][4];
#pragma unroll
        for (int a = 0; a < 4; a++)
#pragma unroll
            for (int e = 0; e < 4; e++) c[a][e] = 0.0f;

#pragma unroll 4
        for (int ks = 0; ks < 16; ks++) {
            const int k0 = ks * 16;
            uint32_t aH[4], aL[4];
            ldsm4(sb + (aRow * QSTR + k0 + aCol8) * 2, aH);
            ldsm4(sb + (QELE + aRow * QSTR + k0 + aCol8) * 2, aL);
#pragma unroll
            for (int pair = 0; pair < 2; pair++) {
                const int j0 = wc * 32 + pair * 16;
                uint32_t bH[4], bL[4];
                ldsm4(sb + (kh + (j0 + bRowQK) * QSTR + k0 + bColQK8) * 2, bH);
                ldsm4(sb + (kl + (j0 + bRowQK) * QSTR + k0 + bColQK8) * 2, bL);
#pragma unroll
                for (int s2 = 0; s2 < 2; s2++) {
                    float* cc = c[pair * 2 + s2];
                    mma_bf16(cc, aH, bH + s2 * 2);
                    mma_bf16(cc, aH, bL + s2 * 2);
                    mma_bf16(cc, aL, bH + s2 * 2);
                }
            }
        }

        if (kb < qb) issue_kv(cur ^ 1, kb + 1);
        else asm volatile("cp.async.commit_group;");

        const bool diag = (kb == qb);
#pragma unroll
        for (int a = 0; a < 4; a++) {
            int colb = kb * 64 + wc * 32 + a * 8 + 2 * tc;
            c[a][0] *= SCL; c[a][1] *= SCL; c[a][2] *= SCL; c[a][3] *= SCL;
            if (diag) {
                if (colb     > grow0) c[a][0] = -3.0e38f;
                if (colb + 1 > grow0) c[a][1] = -3.0e38f;
                if (colb     > grow1) c[a][2] = -3.0e38f;
                if (colb + 1 > grow1) c[a][3] = -3.0e38f;
            }
        }

        float tmax0 = -3.0e38f, tmax1 = -3.0e38f;
#pragma unroll
        for (int a = 0; a < 4; a++) {
            tmax0 = fmaxf(tmax0, fmaxf(c[a][0], c[a][1]));
            tmax1 = fmaxf(tmax1, fmaxf(c[a][2], c[a][3]));
        }
        tmax0 = fmaxf(tmax0, __shfl_xor_sync(0xffffffffu, tmax0, 1));
        tmax0 = fmaxf(tmax0, __shfl_xor_sync(0xffffffffu, tmax0, 2));
        tmax1 = fmaxf(tmax1, __shfl_xor_sync(0xffffffffu, tmax1, 1));
        tmax1 = fmaxf(tmax1, __shfl_xor_sync(0xffffffffu, tmax1, 2));
        if (tc == 0) {
            red[0][wc][lrow0] = tmax0;
            red[0][wc][lrow0 + 8] = tmax1;
        }
        __syncthreads();
        float mn0 = fmaxf(m0, fmaxf(red[0][0][lrow0], red[0][1][lrow0]));
        float mn1 = fmaxf(m1, fmaxf(red[0][0][lrow0 + 8], red[0][1][lrow0 + 8]));
        float alpha0 = __expf(m0 - mn0);
        float alpha1 = __expf(m1 - mn1);
#pragma unroll
        for (int a = 0; a < 16; a++) {
            Ot[a][0] *= alpha0; Ot[a][1] *= alpha0;
            Ot[a][2] *= alpha1; Ot[a][3] *= alpha1;
        }
        float tsum0 = 0.0f, tsum1 = 0.0f;
#pragma unroll
        for (int a = 0; a < 4; a++) {
            c[a][0] = __expf(c[a][0] - mn0);
            c[a][1] = __expf(c[a][1] - mn0);
            c[a][2] = __expf(c[a][2] - mn1);
            c[a][3] = __expf(c[a][3] - mn1);
            tsum0 += c[a][0] + c[a][1];
            tsum1 += c[a][2] + c[a][3];
        }
        tsum0 += __shfl_xor_sync(0xffffffffu, tsum0, 1);
        tsum0 += __shfl_xor_sync(0xffffffffu, tsum0, 2);
        tsum1 += __shfl_xor_sync(0xffffffffu, tsum1, 1);
        tsum1 += __shfl_xor_sync(0xffffffffu, tsum1, 2);
        if (tc == 0) {
            red[1][wc][lrow0] = tsum0;
            red[1][wc][lrow0 + 8] = tsum1;
        }
#pragma unroll
        for (int a = 0; a < 4; a++) {
            int cbase = wc * 32 + a * 8 + 2 * tc;
            uint32_t ph, pl;
            split2(c[a][0], c[a][1], ph, pl);
            *(uint32_t*)(smem + POFF + lrow0 * PSTR + cbase) = ph;
            *(uint32_t*)(smem + POFF + PELE + lrow0 * PSTR + cbase) = pl;
            split2(c[a][2], c[a][3], ph, pl);
            *(uint32_t*)(smem + POFF + (lrow0 + 8) * PSTR + cbase) = ph;
            *(uint32_t*)(smem + POFF + PELE + (lrow0 + 8) * PSTR + cbase) = pl;
        }
        __syncthreads();
        l0 = l0 * alpha0 + red[1][0][lrow0] + red[1][1][lrow0];
        l1 = l1 * alpha1 + red[1][0][lrow0 + 8] + red[1][1][lrow0 + 8];
        m0 = mn0; m1 = mn1;

#pragma unroll
        for (int ks = 0; ks < 4; ks++) {
            const int k0 = ks * 16;
            uint32_t pH[4], pL[4];
            ldsm4(sb + (POFF + aRow * PSTR + k0 + aCol8) * 2, pH);
            ldsm4(sb + (POFF + PELE + aRow * PSTR + k0 + aCol8) * 2, pL);
#pragma unroll
            for (int pair = 0; pair < 8; pair++) {
                const int n0 = wc * 128 + pair * 16;
                uint32_t vH[4], vL[4];
                ldsm4t(sb + (kh + (k0 + bRowPV) * QSTR + n0 + bColPV8) * 2, vH);
                ldsm4t(sb + (kl + (k0 + bRowPV) * QSTR + n0 + bColPV8) * 2, vL);
#pragma unroll
                for (int s2 = 0; s2 < 2; s2++) {
                    float* oo = Ot[pair * 2 + s2];
                    mma_bf16(oo, pH, vH + s2 * 2);
                    mma_bf16(oo, pH, vL + s2 * 2);
                    mma_bf16(oo, pL, vH + s2 * 2);
                }
            }
        }
        asm volatile("cp.async.wait_group 0;");
        __syncthreads();
    }

    // epilogue: divide by l, fused inverse rope on pe pairs, write [s][h*256+d]
    const float inv0 = 1.0f / l0, inv1 = 1.0f / l1;
#pragma unroll
    for (int a = 0; a < 16; a++) {
        const int d = wc * 128 + a * 8 + 2 * tc;
        float v00 = Ot[a][0] * inv0, v01 = Ot[a][1] * inv0;
        float v10 = Ot[a][2] * inv1, v11 = Ot[a][3] * inv1;
        if (wc == 1 && a >= 8) {
            const int i = (d - NOPE) >> 1;
            float sn, cs, x1, x2;
            sincosf(freqs[grow0 * (RR / 2) + i], &sn, &cs);
            x1 = v00; x2 = v01;
            v00 = fmaf(x1, cs,  x2 * sn);
            v01 = fmaf(x2, cs, -x1 * sn);
            sincosf(freqs[grow1 * (RR / 2) + i], &sn, &cs);
            x1 = v10; x2 = v11;
            v10 = fmaf(x1, cs,  x2 * sn);
            v11 = fmaf(x2, cs, -x1 * sn);
        }
        const int col = h * HD + d;
        *(float2*)&qo[(size_t)grow0 * (NH * HD) + col] = make_float2(v00, v01);
        *(float2*)&qo[(size_t)grow1 * (NH * HD) + col] = make_float2(v10, v11);
    }
}

// ---------------- launch ---------------------------------------------------
extern "C" void kernel_launch(void* const* d_in, const int* in_sizes, int n_in,
                              void* d_out, int out_size)
{
    const float* x         = (const float*)d_in[0];
    const float* freqs     = (const float*)d_in[1];
    const float* wq_a      = (const float*)d_in[2];
    const float* q_norm_w  = (const float*)d_in[3];
    const float* wq_b      = (const float*)d_in[4];
    const float* wkv       = (const float*)d_in[5];
    const float* kv_norm_w = (const float*)d_in[6];
    const float* wo_a_w    = (const float*)d_in[7];
    const float* wo_b      = (const float*)d_in[8];
    const float* attn_sink = (const float*)d_in[9];
    float* out = (float*)d_out;

    float *qap, *qa, *q, *kvp, *orr;
    bf16 *kvh, *kvl;
    cudaGetSymbolAddress((void**)&qap, g_qap);
    cudaGetSymbolAddress((void**)&qa,  g_qa);
    cudaGetSymbolAddress((void**)&q,   g_q);
    cudaGetSymbolAddress((void**)&kvp, g_kvp);
    cudaGetSymbolAddress((void**)&orr, g_or);
    cudaGetSymbolAddress((void**)&kvh, g_kvh);
    cudaGetSymbolAddress((void**)&kvl, g_kvl);

    cudaFuncSetAttribute(gemm_tf32, cudaFuncAttributeMaxDynamicSharedMemorySize, GEMM_SMEM);
    cudaFuncSetAttribute(flash_mma, cudaFuncAttributeMaxDynamicSharedMemorySize, FL_SMEM);

    // q_a partials = x @ wq_a^T, split-K=2 -> [2][2048,1024]
    gemm_tf32<<<dim3(QLAT / TBN, SS / TBM, QSPLIT), 256, GEMM_SMEM>>>( // 0
        x, wq_a, qap, SS, QLAT, HIDD, HIDD, HIDD, QLAT, 0, 0);
    // sum partials + rmsnorm -> qa
    rmsnorm1024<<<SS, 256>>>(qap, q_norm_w, qa);                     // 1
    // q = rms(q_a) @ wq_b^T   [2048,4096]
    gemm_tf32<<<dim3((NH * HD) / TBN, SS / TBM), 256, GEMM_SMEM>>>(  // 2
        qa, wq_b, q, SS, NH * HD, QLAT, QLAT, QLAT, NH * HD, 0, 0);
    // kv partials = x @ wkv^T, split-K=8 -> [8][2048,256]
    gemm_tf32<<<dim3(HD / TBN, SS / TBM, KVSPLIT), 256, GEMM_SMEM>>>( // 3 <- profiled
        x, wkv, kvp, SS, HD, HIDD, HIDD, HIDD, HD, 0, 0);
    kv_norm_rope<<<SS, 64>>>(kvp, kv_norm_w, freqs, kvh, kvl);       // 4
    // flash attention (fused q-prep + inverse rope) in-place on g_q
    flash_mma<<<dim3(SS / 64, NH), 256, FL_SMEM>>>(q, kvh, kvl, freqs, attn_sink); // 5
    // o_r = blockdiag(o @ wo_a^T)  [2048,2048]
    gemm_tf32<<<dim3((NG * ORNK) / TBN, SS / TBM), 256, GEMM_SMEM>>>( // 6
        q, wo_a_w, orr, SS, NG * ORNK, NG * HD, NH * HD, NG * HD, NG * ORNK, ORNK, NG * HD);
    // out = o_r @ wo_b^T [2048,2048]
    gemm_tf32<<<dim3(HIDD / TBN, SS / TBM), 256, GEMM_SMEM>>>(       // 7
        orr, wo_b, out, SS, HIDD, NG * ORNK, NG * ORNK, NG * ORNK, HIDD, 0, 0);
}